// round 1
// baseline (speedup 1.0000x reference)
#include <cuda_runtime.h>

// ============================================================================
// RNN_BN_simple: per-timestep BN -> MLP(64->512->512->64) with train-mode
// BatchNorm, B=4096, T=64.
//
// Structure (9 kernel launches, all graph-capturable, no atomics, no allocs):
//   1. stats(prices)  -> partial sums          (deterministic split reduction)
//   2. finalize0      -> s0,c0 (BN0 folded scale/bias)
//   3. gemm1: h1 = (prices*s0+c0) @ W1 + b1    (prologue-fused BN0)
//   4. stats(h1) / finalize1 -> s1,c1
//   5. gemm2: h2 = relu(h1*s1+c1) @ W2 + b2    (prologue-fused BN1+ReLU)
//   6. stats(h2) / finalize2 -> s2,c2
//   7. gemm3: out = relu(h2*s2+c2) @ W3 + b3   (prologue-fused BN2+ReLU)
//
// GEMMs: fp32 SIMT, 128x128x8 tiles, 8x8 per-thread microtile computed with
// packed fma.rn.f32x2 (sm_100+) for 2x fp32 FMA throughput.
// ============================================================================

namespace {
constexpr int BB = 4096;   // batch
constexpr int TT = 64;     // timesteps
constexpr int PP = 64;     // price dim
constexpr int HH = 512;    // hidden
constexpr float BN_EPS = 1e-3f;
constexpr int SPLITS = 16; // batch splits for stats reduction
}

// ---------------- scratch (static device allocations) ----------------------
__device__ float g_h1[(size_t)TT * BB * HH];          // 512 MB
__device__ float g_h2[(size_t)TT * BB * HH];          // 512 MB
__device__ float g_part_sum[SPLITS * TT * HH];        // partial sums  [split][T*D]
__device__ float g_part_sq [SPLITS * TT * HH];        // partial sumsq
__device__ float g_s[TT * HH];                        // folded BN scale (per stage)
__device__ float g_c[TT * HH];                        // folded BN bias  (per stage)

// ---------------- packed f32x2 helpers --------------------------------------
__device__ __forceinline__ unsigned long long ffma2(unsigned long long a,
                                                    unsigned long long b,
                                                    unsigned long long c) {
    unsigned long long d;
    asm("fma.rn.f32x2 %0, %1, %2, %3;" : "=l"(d) : "l"(a), "l"(b), "l"(c));
    return d;
}
__device__ __forceinline__ unsigned long long dup2(float a) {
    unsigned long long d;
    unsigned u = __float_as_uint(a);
    asm("mov.b64 %0, {%1, %1};" : "=l"(d) : "r"(u));
    return d;
}

// ---------------- BN statistics: deterministic split reduction --------------
// x viewed per-t as [B, D] with element (b, d) at x + t*t_stride + b*row_stride + d.
// grid = (T, SPLITS); each block writes its partial sums (no atomics).
__global__ void stats_kernel(const float* __restrict__ x, size_t t_stride,
                             int row_stride, int D, int rows_per_split) {
    const int t = blockIdx.x;
    const int split = blockIdx.y;
    const float* xt = x + (size_t)t * t_stride +
                      (size_t)split * rows_per_split * row_stride;
    for (int d = threadIdx.x; d < D; d += blockDim.x) {
        float s = 0.f, q = 0.f;
        for (int r = 0; r < rows_per_split; r++) {
            float v = xt[(size_t)r * row_stride + d];
            s += v;
            q = fmaf(v, v, q);
        }
        int n = gridDim.x * D;          // T*D
        int i = t * D + d;
        g_part_sum[split * n + i] = s;
        g_part_sq [split * n + i] = q;
    }
}

// folded scale/bias: s = g * rsqrt(var + eps); c = beta - mean * s
__global__ void finalize_kernel(const float* __restrict__ gamma,
                                const float* __restrict__ beta,
                                int n, float invB) {
    int i = blockIdx.x * blockDim.x + threadIdx.x;
    if (i >= n) return;
    float s = 0.f, q = 0.f;
    #pragma unroll
    for (int sp = 0; sp < SPLITS; sp++) {
        s += g_part_sum[sp * n + i];
        q += g_part_sq [sp * n + i];
    }
    float m = s * invB;
    float v = fmaf(-m, m, q * invB);
    v = fmaxf(v, 0.f);
    float sc = gamma[i] * rsqrtf(v + BN_EPS);
    g_s[i] = sc;
    g_c[i] = fmaf(-m, sc, beta[i]);
}

// ---------------- fused GEMM ------------------------------------------------
// out[t, m, n] = sum_k pre(A[t, m, k]) * W[t, k, n] + bias[t, n]
// pre(a) = (relu?)(a * g_s[t*K+k] + g_c[t*K+k])
template <int BM, int BN, int BK, bool PRE_RELU, int KTOT, int NTOT>
__global__ void __launch_bounds__((BM / 8) * (BN / 8), 2)
gemm_fused(const float* __restrict__ A, size_t a_t, int a_rs,
           const float* __restrict__ W, const float* __restrict__ bias,
           float* __restrict__ out, size_t o_t, int o_rs) {
    constexpr int THREADS = (BM / 8) * (BN / 8);
    constexpr int AV = BM * BK / (4 * THREADS);
    constexpr int WV = BK * BN / (4 * THREADS);
    constexpr int KT = KTOT / BK;

    __shared__ __align__(16) float As[BK][BM + 4];
    __shared__ __align__(16) float Ws[BK][BN];

    const int t  = blockIdx.z;
    const int n0 = blockIdx.x * BN;
    const int m0 = blockIdx.y * BM;
    const int tid = threadIdx.x;
    const int tx = tid % (BN / 8);
    const int ty = tid / (BN / 8);

    const float* At = A + (size_t)t * a_t + (size_t)m0 * a_rs;
    const float* Wt = W + (size_t)t * KTOT * NTOT + n0;
    const float* sp = g_s + t * KTOT;
    const float* cp = g_c + t * KTOT;

    int a_m[AV], a_kq[AV], w_k[WV], w_nq[WV];
    #pragma unroll
    for (int v = 0; v < AV; v++) {
        int i = v * THREADS + tid;
        a_kq[v] = i % (BK / 4);
        a_m[v]  = i / (BK / 4);
    }
    #pragma unroll
    for (int v = 0; v < WV; v++) {
        int i = v * THREADS + tid;
        w_nq[v] = i % (BN / 4);
        w_k[v]  = i / (BN / 4);
    }

    float4 a_reg[AV], s_reg[AV], c_reg[AV], w_reg[WV];

    auto load = [&](int kt) {
        #pragma unroll
        for (int v = 0; v < AV; v++) {
            int kg = kt * BK + a_kq[v] * 4;
            a_reg[v] = *(const float4*)(At + (size_t)a_m[v] * a_rs + kg);
            s_reg[v] = *(const float4*)(sp + kg);
            c_reg[v] = *(const float4*)(cp + kg);
        }
        #pragma unroll
        for (int v = 0; v < WV; v++) {
            w_reg[v] = *(const float4*)(Wt + (size_t)(kt * BK + w_k[v]) * NTOT +
                                        w_nq[v] * 4);
        }
    };

    auto stash = [&]() {
        #pragma unroll
        for (int v = 0; v < AV; v++) {
            float av[4] = {a_reg[v].x, a_reg[v].y, a_reg[v].z, a_reg[v].w};
            float sv[4] = {s_reg[v].x, s_reg[v].y, s_reg[v].z, s_reg[v].w};
            float cv[4] = {c_reg[v].x, c_reg[v].y, c_reg[v].z, c_reg[v].w};
            #pragma unroll
            for (int j = 0; j < 4; j++) {
                float val = fmaf(av[j], sv[j], cv[j]);
                if (PRE_RELU) val = fmaxf(val, 0.0f);
                As[a_kq[v] * 4 + j][a_m[v]] = val;
            }
        }
        #pragma unroll
        for (int v = 0; v < WV; v++) {
            *(float4*)&Ws[w_k[v]][w_nq[v] * 4] = w_reg[v];
        }
    };

    unsigned long long acc[8][4];
    #pragma unroll
    for (int i = 0; i < 8; i++)
        #pragma unroll
        for (int j = 0; j < 4; j++) acc[i][j] = 0ULL;

    load(0);
    #pragma unroll 1
    for (int kt = 0; kt < KT; kt++) {
        __syncthreads();
        stash();
        __syncthreads();
        if (kt + 1 < KT) load(kt + 1);
        #pragma unroll
        for (int k = 0; k < BK; k++) {
            float4 a0 = *(const float4*)&As[k][ty * 8];
            float4 a1 = *(const float4*)&As[k][ty * 8 + 4];
            ulonglong2 b01 = *(const ulonglong2*)&Ws[k][tx * 8];
            ulonglong2 b23 = *(const ulonglong2*)&Ws[k][tx * 8 + 4];
            float af[8] = {a0.x, a0.y, a0.z, a0.w, a1.x, a1.y, a1.z, a1.w};
            #pragma unroll
            for (int i = 0; i < 8; i++) {
                unsigned long long ad = dup2(af[i]);
                acc[i][0] = ffma2(ad, b01.x, acc[i][0]);
                acc[i][1] = ffma2(ad, b01.y, acc[i][1]);
                acc[i][2] = ffma2(ad, b23.x, acc[i][2]);
                acc[i][3] = ffma2(ad, b23.y, acc[i][3]);
            }
        }
    }

    // epilogue: add bias, store
    const float* bt = bias + t * NTOT + n0 + tx * 8;
    float4 bv0 = *(const float4*)bt;
    float4 bv1 = *(const float4*)(bt + 4);
    float bv[8] = {bv0.x, bv0.y, bv0.z, bv0.w, bv1.x, bv1.y, bv1.z, bv1.w};
    #pragma unroll
    for (int i = 0; i < 8; i++) {
        float r[8];
        #pragma unroll
        for (int jp = 0; jp < 4; jp++) {
            unsigned long long p = acc[i][jp];
            r[2 * jp]     = __uint_as_float((unsigned)(p & 0xffffffffULL)) + bv[2 * jp];
            r[2 * jp + 1] = __uint_as_float((unsigned)(p >> 32))           + bv[2 * jp + 1];
        }
        float* o = out + (size_t)t * o_t + (size_t)(m0 + ty * 8 + i) * o_rs +
                   n0 + tx * 8;
        *(float4*)o       = make_float4(r[0], r[1], r[2], r[3]);
        *(float4*)(o + 4) = make_float4(r[4], r[5], r[6], r[7]);
    }
}

// ---------------- launch ----------------------------------------------------
extern "C" void kernel_launch(void* const* d_in, const int* in_sizes, int n_in,
                              void* d_out, int out_size) {
    (void)in_sizes; (void)n_in; (void)out_size;
    const float* prices = (const float*)d_in[0];
    const float* bn0_g  = (const float*)d_in[1];
    const float* bn0_b  = (const float*)d_in[2];
    const float* W1     = (const float*)d_in[3];
    const float* b1     = (const float*)d_in[4];
    const float* bn1_g  = (const float*)d_in[5];
    const float* bn1_b  = (const float*)d_in[6];
    const float* W2     = (const float*)d_in[7];
    const float* b2     = (const float*)d_in[8];
    const float* bn2_g  = (const float*)d_in[9];
    const float* bn2_b  = (const float*)d_in[10];
    const float* W3     = (const float*)d_in[11];
    const float* b3     = (const float*)d_in[12];
    float* out = (float*)d_out;

    float* h1p = nullptr;
    float* h2p = nullptr;
    cudaGetSymbolAddress((void**)&h1p, g_h1);
    cudaGetSymbolAddress((void**)&h2p, g_h2);

    const float invB = 1.0f / (float)BB;
    const int rps = BB / SPLITS;

    // stage 0: BN0 on prices [B, T, P]  (per-t row stride T*P, t offset P)
    stats_kernel<<<dim3(TT, SPLITS), 64>>>(prices, (size_t)PP, TT * PP, PP, rps);
    finalize_kernel<<<(TT * PP + 255) / 256, 256>>>(bn0_g, bn0_b, TT * PP, invB);

    // gemm1: h1[t, b, h] = bn0(prices) @ W1 + b1    (M=4096, N=512, K=64)
    gemm_fused<128, 128, 8, false, PP, HH>
        <<<dim3(HH / 128, BB / 128, TT), 256>>>(
            prices, (size_t)PP, TT * PP, W1, b1, h1p, (size_t)BB * HH, HH);

    // stage 1: BN1 on h1 [T, B, H]
    stats_kernel<<<dim3(TT, SPLITS), 256>>>(h1p, (size_t)BB * HH, HH, HH, rps);
    finalize_kernel<<<(TT * HH + 255) / 256, 256>>>(bn1_g, bn1_b, TT * HH, invB);

    // gemm2: h2 = relu(bn1(h1)) @ W2 + b2           (M=4096, N=512, K=512)
    gemm_fused<128, 128, 8, true, HH, HH>
        <<<dim3(HH / 128, BB / 128, TT), 256>>>(
            h1p, (size_t)BB * HH, HH, W2, b2, h2p, (size_t)BB * HH, HH);

    // stage 2: BN2 on h2 [T, B, H]
    stats_kernel<<<dim3(TT, SPLITS), 256>>>(h2p, (size_t)BB * HH, HH, HH, rps);
    finalize_kernel<<<(TT * HH + 255) / 256, 256>>>(bn2_g, bn2_b, TT * HH, invB);

    // gemm3: out[b, t, p] = relu(bn2(h2)) @ W3 + b3 (M=4096, N=64, K=512)
    gemm_fused<128, 64, 8, true, HH, PP>
        <<<dim3(1, BB / 128, TT), 128>>>(
            h2p, (size_t)BB * HH, HH, W3, b3, out, (size_t)PP, TT * PP);
}

// round 3
// speedup vs baseline: 1.5112x; 1.5112x over previous
#include <cuda_runtime.h>
#include <cuda_bf16.h>
#include <cstdint>

// ============================================================================
// RNN_BN_simple via mma.sync (HMMA) split-bf16 GEMMs on sm_103.
// (tcgen05 is rejected by this bench's ptxas target 'sm_103' — no 'a' suffix —
//  so the tensor path uses arch-agnostic ldmatrix + mma.sync.m16n8k16.bf16.)
//
// Numerics: x*w ~= xh*wh + xh*wl + xl*wh with fp32 accumulation (err ~2^-16).
// BN is folded into the GEMM A-prologue (scale s, bias c precomputed).
// ============================================================================

namespace {
constexpr int BB = 4096;
constexpr int TT = 64;
constexpr int PP = 64;
constexpr int HH = 512;
constexpr float BN_EPS = 1e-3f;
constexpr int SPLITS = 16;
}

// ---------------- scratch ----------------------------------------------------
__device__ float g_h1[(size_t)TT * BB * HH];
__device__ float g_h2[(size_t)TT * BB * HH];
__device__ float g_part_sum[SPLITS * TT * HH];
__device__ float g_part_sq [SPLITS * TT * HH];
__device__ float g_s[TT * HH];
__device__ float g_c[TT * HH];
// weights as bf16 hi/lo, same [T, K, N] layout as the fp32 source
__device__ __align__(16) __nv_bfloat16 g_w1hi[(size_t)TT * PP * HH];
__device__ __align__(16) __nv_bfloat16 g_w1lo[(size_t)TT * PP * HH];
__device__ __align__(16) __nv_bfloat16 g_w2hi[(size_t)TT * HH * HH];
__device__ __align__(16) __nv_bfloat16 g_w2lo[(size_t)TT * HH * HH];
__device__ __align__(16) __nv_bfloat16 g_w3hi[(size_t)TT * HH * PP];
__device__ __align__(16) __nv_bfloat16 g_w3lo[(size_t)TT * HH * PP];

// ---------------- helpers ------------------------------------------------------
__device__ __forceinline__ uint32_t smem_u32(const void* p) {
    uint32_t a;
    asm("{ .reg .u64 t; cvta.to.shared.u64 t, %1; cvt.u32.u64 %0, t; }"
        : "=r"(a) : "l"(p));
    return a;
}
__device__ __forceinline__ void ldm_x4(uint32_t* r, uint32_t addr) {
    asm volatile("ldmatrix.sync.aligned.m8n8.x4.shared.b16 {%0,%1,%2,%3}, [%4];"
                 : "=r"(r[0]), "=r"(r[1]), "=r"(r[2]), "=r"(r[3]) : "r"(addr));
}
__device__ __forceinline__ void ldm_x4t(uint32_t* r, uint32_t addr) {
    asm volatile("ldmatrix.sync.aligned.m8n8.x4.trans.shared.b16 {%0,%1,%2,%3}, [%4];"
                 : "=r"(r[0]), "=r"(r[1]), "=r"(r[2]), "=r"(r[3]) : "r"(addr));
}
__device__ __forceinline__ void mma_bf16(float* c, const uint32_t* a,
                                         const uint32_t* b) {
    asm volatile(
        "mma.sync.aligned.m16n8k16.row.col.f32.bf16.bf16.f32 "
        "{%0,%1,%2,%3}, {%4,%5,%6,%7}, {%8,%9}, {%0,%1,%2,%3};"
        : "+f"(c[0]), "+f"(c[1]), "+f"(c[2]), "+f"(c[3])
        : "r"(a[0]), "r"(a[1]), "r"(a[2]), "r"(a[3]), "r"(b[0]), "r"(b[1]));
}
__device__ __forceinline__ void cp16(uint32_t dst, const void* src) {
    asm volatile("cp.async.cg.shared.global [%0], [%1], 16;"
                 :: "r"(dst), "l"(src));
}
__device__ __forceinline__ unsigned short bfu(__nv_bfloat16 h) {
    __nv_bfloat16_raw r = h; return r.x;
}

// ---------------- BN stats -------------------------------------------------------
__global__ void stats_kernel(const float* __restrict__ x, size_t t_stride,
                             int row_stride, int D, int rows_per_split) {
    const int t = blockIdx.x, split = blockIdx.y;
    const float* xt = x + (size_t)t * t_stride +
                      (size_t)split * rows_per_split * row_stride;
    for (int d = threadIdx.x; d < D; d += blockDim.x) {
        float s = 0.f, q = 0.f;
        for (int r = 0; r < rows_per_split; r++) {
            float v = xt[(size_t)r * row_stride + d];
            s += v; q = fmaf(v, v, q);
        }
        int n = gridDim.x * D, i = t * D + d;
        g_part_sum[split * n + i] = s;
        g_part_sq [split * n + i] = q;
    }
}
__global__ void finalize_kernel(const float* __restrict__ gamma,
                                const float* __restrict__ beta, int n, float invB) {
    int i = blockIdx.x * blockDim.x + threadIdx.x;
    if (i >= n) return;
    float s = 0.f, q = 0.f;
    #pragma unroll
    for (int sp = 0; sp < SPLITS; sp++) { s += g_part_sum[sp*n+i]; q += g_part_sq[sp*n+i]; }
    float m = s * invB;
    float v = fmaxf(fmaf(-m, m, q * invB), 0.f);
    float sc = gamma[i] * rsqrtf(v + BN_EPS);
    g_s[i] = sc;
    g_c[i] = fmaf(-m, sc, beta[i]);
}

// ---------------- weight prep: fp32 -> bf16 hi/lo (same layout) -------------------
__global__ void prep_w(const float* __restrict__ W, __nv_bfloat16* __restrict__ hi,
                       __nv_bfloat16* __restrict__ lo, size_t nq) {
    size_t i = (size_t)blockIdx.x * blockDim.x + threadIdx.x;
    if (i >= nq) return;
    float4 w = ((const float4*)W)[i];
    float wv[4] = {w.x, w.y, w.z, w.w};
    unsigned short hs[4], ls[4];
    #pragma unroll
    for (int j = 0; j < 4; j++) {
        __nv_bfloat16 h = __float2bfloat16(wv[j]);
        hs[j] = bfu(h);
        ls[j] = bfu(__float2bfloat16(wv[j] - __bfloat162float(h)));
    }
    ((uint2*)hi)[i] = make_uint2(hs[0] | (hs[1] << 16), hs[2] | (hs[3] << 16));
    ((uint2*)lo)[i] = make_uint2(ls[0] | (ls[1] << 16), ls[2] | (ls[3] << 16));
}

// ---------------- split-bf16 HMMA GEMM ---------------------------------------------
// out[t, m, n] = sum_k prelu(A[t,m,k]*s[t,k]+c[t,k]) * W[t,k,n] + bias[t,n]
template <int BN, int KTOT, int NTOT, bool RELU, int WARPS_M, int WARPS_N>
__global__ void __launch_bounds__(256)
gemm_mma(const float* __restrict__ A, size_t a_t, int a_rs,
         const __nv_bfloat16* __restrict__ Whi,
         const __nv_bfloat16* __restrict__ Wlo,
         const float* __restrict__ bias,
         float* __restrict__ out, size_t o_t, int o_rs) {
    constexpr int BM = 128, BK = 32;
    constexpr int AROW = BK + 8;               // bf16 elems per A smem row
    constexpr int WROW = BN + 8;               // bf16 elems per W smem row
    constexpr int A_BYTES = BM * AROW * 2;
    constexpr int W_BYTES = BK * WROW * 2;
    constexpr int STAGE = 2 * A_BYTES + 2 * W_BYTES;
    constexpr int AH = 0, AL = A_BYTES, WHO = 2 * A_BYTES, WLO = 2 * A_BYTES + W_BYTES;
    constexpr int KT = KTOT / BK;
    constexpr int WTM = BM / WARPS_M, WTN = BN / WARPS_N;
    constexpr int MT = WTM / 16, NT = WTN / 8;
    constexpr int SEGS = BN / 8;               // 16B segments per W row

    extern __shared__ char smem[];
    const uint32_t sb = smem_u32(smem);
    const int tid = threadIdx.x;
    const int wid = tid >> 5, lane = tid & 31;
    const int wm = wid / WARPS_N, wn = wid % WARPS_N;

    const int t = blockIdx.z;
    const int n0 = blockIdx.x * BN;
    const int m0 = blockIdx.y * BM;

    const float* sArr = g_s + t * KTOT;
    const float* cArr = g_c + t * KTOT;
    const float* At = A + (size_t)t * a_t + (size_t)m0 * a_rs;
    const __nv_bfloat16* WhT = Whi + (size_t)t * KTOT * NTOT + n0;
    const __nv_bfloat16* WlT = Wlo + (size_t)t * KTOT * NTOT + n0;

    auto load_chunk = [&](int kt, int st) {
        const uint32_t stb = sb + st * STAGE;
        // W tiles (cp.async, rows contiguous in global N)
        #pragma unroll
        for (int i = tid; i < BK * SEGS; i += 256) {
            int row = i / SEGS, seg = i % SEGS;
            size_t goff = (size_t)(kt * BK + row) * NTOT + seg * 8;
            uint32_t doff = row * (WROW * 2) + seg * 16;
            cp16(stb + WHO + doff, WhT + goff);
            cp16(stb + WLO + doff, WlT + goff);
        }
        asm volatile("cp.async.commit_group;" ::: "memory");
        // A tile: fp32 -> BN affine (+relu) -> hi/lo bf16 -> STS
        #pragma unroll
        for (int v = 0; v < BM * (BK / 4) / 256; v++) {
            int q = v * 256 + tid;
            int row = q / (BK / 4), kq = q % (BK / 4);
            float4 x = *(const float4*)(At + (size_t)row * a_rs + kt * BK + kq * 4);
            float4 sv = *(const float4*)(sArr + kt * BK + kq * 4);
            float4 cv = *(const float4*)(cArr + kt * BK + kq * 4);
            float y[4] = {fmaf(x.x, sv.x, cv.x), fmaf(x.y, sv.y, cv.y),
                          fmaf(x.z, sv.z, cv.z), fmaf(x.w, sv.w, cv.w)};
            unsigned short hs[4], ls[4];
            #pragma unroll
            for (int j = 0; j < 4; j++) {
                if (RELU) y[j] = fmaxf(y[j], 0.f);
                __nv_bfloat16 h = __float2bfloat16(y[j]);
                hs[j] = bfu(h);
                ls[j] = bfu(__float2bfloat16(y[j] - __bfloat162float(h)));
            }
            uint32_t doff = (row * AROW + kq * 4) * 2;
            *(uint2*)(smem + st * STAGE + AH + doff) =
                make_uint2(hs[0] | (hs[1] << 16), hs[2] | (hs[3] << 16));
            *(uint2*)(smem + st * STAGE + AL + doff) =
                make_uint2(ls[0] | (ls[1] << 16), ls[2] | (ls[3] << 16));
        }
    };

    float acc[MT][NT][4];
    #pragma unroll
    for (int i = 0; i < MT; i++)
        #pragma unroll
        for (int j = 0; j < NT; j++)
            #pragma unroll
            for (int k = 0; k < 4; k++) acc[i][j][k] = 0.f;

    load_chunk(0, 0);

    #pragma unroll 1
    for (int kt = 0; kt < KT; kt++) {
        const int st = kt & 1;
        if (kt + 1 < KT) load_chunk(kt + 1, st ^ 1);
        if (kt + 1 < KT) asm volatile("cp.async.wait_group 1;" ::: "memory");
        else             asm volatile("cp.async.wait_group 0;" ::: "memory");
        __syncthreads();

        const uint32_t stb = sb + st * STAGE;
        // lane-derived ldmatrix addresses
        const int lrow = lane & 15, lsel = lane >> 4;
        #pragma unroll
        for (int k16 = 0; k16 < 2; k16++) {
            uint32_t ah[MT][4], al[MT][4];
            #pragma unroll
            for (int mt = 0; mt < MT; mt++) {
                uint32_t off =
                    ((wm * WTM + mt * 16 + lrow) * AROW + k16 * 16 + lsel * 8) * 2;
                ldm_x4(ah[mt], stb + AH + off);
                ldm_x4(al[mt], stb + AL + off);
            }
            uint32_t bh[NT][2], bl[NT][2];
            #pragma unroll
            for (int np = 0; np < NT / 2; np++) {
                uint32_t off =
                    ((k16 * 16 + lrow) * WROW + wn * WTN + np * 16 + lsel * 8) * 2;
                uint32_t r[4];
                ldm_x4t(r, stb + WHO + off);
                bh[2*np][0] = r[0]; bh[2*np][1] = r[1];
                bh[2*np+1][0] = r[2]; bh[2*np+1][1] = r[3];
                ldm_x4t(r, stb + WLO + off);
                bl[2*np][0] = r[0]; bl[2*np][1] = r[1];
                bl[2*np+1][0] = r[2]; bl[2*np+1][1] = r[3];
            }
            #pragma unroll
            for (int mt = 0; mt < MT; mt++)
                #pragma unroll
                for (int nt = 0; nt < NT; nt++) {
                    mma_bf16(acc[mt][nt], ah[mt], bh[nt]);
                    mma_bf16(acc[mt][nt], ah[mt], bl[nt]);
                    mma_bf16(acc[mt][nt], al[mt], bh[nt]);
                }
        }
        __syncthreads();
    }

    // epilogue: add bias, store fp32
    const int r0 = lane >> 2, c0 = (lane & 3) * 2;
    #pragma unroll
    for (int mt = 0; mt < MT; mt++) {
        #pragma unroll
        for (int nt = 0; nt < NT; nt++) {
            int col = n0 + wn * WTN + nt * 8 + c0;
            float2 bv = *(const float2*)(bias + t * NTOT + col);
            int row = m0 + wm * WTM + mt * 16 + r0;
            float* p0 = out + (size_t)t * o_t + (size_t)row * o_rs + col;
            float* p1 = p0 + (size_t)8 * o_rs;
            *(float2*)p0 = make_float2(acc[mt][nt][0] + bv.x, acc[mt][nt][1] + bv.y);
            *(float2*)p1 = make_float2(acc[mt][nt][2] + bv.x, acc[mt][nt][3] + bv.y);
        }
    }
}

// ---------------- launch -------------------------------------------------------
extern "C" void kernel_launch(void* const* d_in, const int* in_sizes, int n_in,
                              void* d_out, int out_size) {
    (void)in_sizes; (void)n_in; (void)out_size;
    const float* prices = (const float*)d_in[0];
    const float* bn0_g  = (const float*)d_in[1];
    const float* bn0_b  = (const float*)d_in[2];
    const float* W1     = (const float*)d_in[3];
    const float* b1     = (const float*)d_in[4];
    const float* bn1_g  = (const float*)d_in[5];
    const float* bn1_b  = (const float*)d_in[6];
    const float* W2     = (const float*)d_in[7];
    const float* b2     = (const float*)d_in[8];
    const float* bn2_g  = (const float*)d_in[9];
    const float* bn2_b  = (const float*)d_in[10];
    const float* W3     = (const float*)d_in[11];
    const float* b3     = (const float*)d_in[12];
    float* out = (float*)d_out;

    float *h1p, *h2p;
    __nv_bfloat16 *w1h, *w1l, *w2h, *w2l, *w3h, *w3l;
    cudaGetSymbolAddress((void**)&h1p, g_h1);
    cudaGetSymbolAddress((void**)&h2p, g_h2);
    cudaGetSymbolAddress((void**)&w1h, g_w1hi);
    cudaGetSymbolAddress((void**)&w1l, g_w1lo);
    cudaGetSymbolAddress((void**)&w2h, g_w2hi);
    cudaGetSymbolAddress((void**)&w2l, g_w2lo);
    cudaGetSymbolAddress((void**)&w3h, g_w3hi);
    cudaGetSymbolAddress((void**)&w3l, g_w3lo);

    const float invB = 1.0f / (float)BB;
    const int rps = BB / SPLITS;

    auto g1 = gemm_mma<128, PP, HH, false, 2, 4>;
    auto g2 = gemm_mma<128, HH, HH, true,  2, 4>;
    auto g3 = gemm_mma<64,  HH, PP, true,  4, 2>;
    // STAGE sizes: A 2*128*40*2 = 20480 per stage-half; W 2*32*(BN+8)*2
    constexpr int SM12 = 2 * (2 * 128 * 40 * 2 + 2 * 32 * 136 * 2); // 75776
    constexpr int SM3  = 2 * (2 * 128 * 40 * 2 + 2 * 32 * 72 * 2);  // 59392
    cudaFuncSetAttribute(g1, cudaFuncAttributeMaxDynamicSharedMemorySize, SM12);
    cudaFuncSetAttribute(g2, cudaFuncAttributeMaxDynamicSharedMemorySize, SM12);
    cudaFuncSetAttribute(g3, cudaFuncAttributeMaxDynamicSharedMemorySize, SM3);

    // weight prep
    prep_w<<<(int)(((size_t)TT*PP*HH/4 + 255)/256), 256>>>(W1, w1h, w1l, (size_t)TT*PP*HH/4);
    prep_w<<<(int)(((size_t)TT*HH*HH/4 + 255)/256), 256>>>(W2, w2h, w2l, (size_t)TT*HH*HH/4);
    prep_w<<<(int)(((size_t)TT*HH*PP/4 + 255)/256), 256>>>(W3, w3h, w3l, (size_t)TT*HH*PP/4);

    // BN0 -> gemm1
    stats_kernel<<<dim3(TT, SPLITS), 64>>>(prices, (size_t)PP, TT * PP, PP, rps);
    finalize_kernel<<<(TT * PP + 255) / 256, 256>>>(bn0_g, bn0_b, TT * PP, invB);
    g1<<<dim3(HH / 128, BB / 128, TT), 256, SM12>>>(
        prices, (size_t)PP, TT * PP, w1h, w1l, b1, h1p, (size_t)BB * HH, HH);
    // BN1 -> gemm2
    stats_kernel<<<dim3(TT, SPLITS), 256>>>(h1p, (size_t)BB * HH, HH, HH, rps);
    finalize_kernel<<<(TT * HH + 255) / 256, 256>>>(bn1_g, bn1_b, TT * HH, invB);
    g2<<<dim3(HH / 128, BB / 128, TT), 256, SM12>>>(
        h1p, (size_t)BB * HH, HH, w2h, w2l, b2, h2p, (size_t)BB * HH, HH);
    // BN2 -> gemm3
    stats_kernel<<<dim3(TT, SPLITS), 256>>>(h2p, (size_t)BB * HH, HH, HH, rps);
    finalize_kernel<<<(TT * HH + 255) / 256, 256>>>(bn2_g, bn2_b, TT * HH, invB);
    g3<<<dim3(1, BB / 128, TT), 256, SM3>>>(
        h2p, (size_t)BB * HH, HH, w3h, w3l, b3, out, (size_t)PP, TT * PP);
}

// round 4
// speedup vs baseline: 2.1156x; 1.3999x over previous
#include <cuda_runtime.h>
#include <cuda_bf16.h>
#include <cstdint>

// ============================================================================
// RNN_BN_simple, round 4: lean HMMA GEMMs.
//  - Activations pre-converted (BN affine + ReLU + hi/lo bf16 split) by
//    elementwise conv kernels -> GEMM mainloop is cp.async + ldmatrix + HMMA.
//  - BN batch stats computed in the GEMM epilogue (deterministic partials per
//    m-block), finalize folds them to scale/bias.
//  - Split-bf16: x*w ~= xh*wh + xh*wl + xl*wh, fp32 accumulation.
// ============================================================================

namespace {
constexpr int BB = 4096, TT = 64, PP = 64, HH = 512;
constexpr float BN_EPS = 1e-3f;
constexpr int SPLITS0 = 16;      // price-stats splits
constexpr int MBLK = BB / 128;   // 32 epilogue partial blocks
}

// ---------------- scratch ----------------------------------------------------
__device__ float g_h[(size_t)TT * BB * HH];                    // raw pre-BN h (reused)
__device__ __align__(16) __nv_bfloat16 g_yhi[(size_t)TT * BB * HH];
__device__ __align__(16) __nv_bfloat16 g_ylo[(size_t)TT * BB * HH];
__device__ float g_psum[MBLK * TT * HH];
__device__ float g_psq [MBLK * TT * HH];
__device__ float g_s[TT * HH];
__device__ float g_c[TT * HH];
__device__ __align__(16) __nv_bfloat16 g_w1hi[(size_t)TT * PP * HH];
__device__ __align__(16) __nv_bfloat16 g_w1lo[(size_t)TT * PP * HH];
__device__ __align__(16) __nv_bfloat16 g_w2hi[(size_t)TT * HH * HH];
__device__ __align__(16) __nv_bfloat16 g_w2lo[(size_t)TT * HH * HH];
__device__ __align__(16) __nv_bfloat16 g_w3hi[(size_t)TT * HH * PP];
__device__ __align__(16) __nv_bfloat16 g_w3lo[(size_t)TT * HH * PP];

// ---------------- helpers ------------------------------------------------------
__device__ __forceinline__ uint32_t smem_u32(const void* p) {
    uint32_t a;
    asm("{ .reg .u64 t; cvta.to.shared.u64 t, %1; cvt.u32.u64 %0, t; }"
        : "=r"(a) : "l"(p));
    return a;
}
__device__ __forceinline__ void ldm_x4(uint32_t* r, uint32_t addr) {
    asm volatile("ldmatrix.sync.aligned.m8n8.x4.shared.b16 {%0,%1,%2,%3}, [%4];"
                 : "=r"(r[0]), "=r"(r[1]), "=r"(r[2]), "=r"(r[3]) : "r"(addr));
}
__device__ __forceinline__ void ldm_x4t(uint32_t* r, uint32_t addr) {
    asm volatile("ldmatrix.sync.aligned.m8n8.x4.trans.shared.b16 {%0,%1,%2,%3}, [%4];"
                 : "=r"(r[0]), "=r"(r[1]), "=r"(r[2]), "=r"(r[3]) : "r"(addr));
}
__device__ __forceinline__ void mma_bf16(float* c, const uint32_t* a,
                                         const uint32_t* b) {
    asm volatile(
        "mma.sync.aligned.m16n8k16.row.col.f32.bf16.bf16.f32 "
        "{%0,%1,%2,%3}, {%4,%5,%6,%7}, {%8,%9}, {%0,%1,%2,%3};"
        : "+f"(c[0]), "+f"(c[1]), "+f"(c[2]), "+f"(c[3])
        : "r"(a[0]), "r"(a[1]), "r"(a[2]), "r"(a[3]), "r"(b[0]), "r"(b[1]));
}
__device__ __forceinline__ void cp16(uint32_t dst, const void* src) {
    asm volatile("cp.async.cg.shared.global [%0], [%1], 16;"
                 :: "r"(dst), "l"(src));
}
__device__ __forceinline__ unsigned short bfu(__nv_bfloat16 h) {
    __nv_bfloat16_raw r = h; return r.x;
}
__device__ __forceinline__ void split4(float y0, float y1, float y2, float y3,
                                       uint2& hp, uint2& lp) {
    __nv_bfloat16 h0 = __float2bfloat16(y0), h1 = __float2bfloat16(y1);
    __nv_bfloat16 h2 = __float2bfloat16(y2), h3 = __float2bfloat16(y3);
    unsigned short l0 = bfu(__float2bfloat16(y0 - __bfloat162float(h0)));
    unsigned short l1 = bfu(__float2bfloat16(y1 - __bfloat162float(h1)));
    unsigned short l2 = bfu(__float2bfloat16(y2 - __bfloat162float(h2)));
    unsigned short l3 = bfu(__float2bfloat16(y3 - __bfloat162float(h3)));
    hp = make_uint2(bfu(h0) | ((uint32_t)bfu(h1) << 16),
                    bfu(h2) | ((uint32_t)bfu(h3) << 16));
    lp = make_uint2(l0 | ((uint32_t)l1 << 16), l2 | ((uint32_t)l3 << 16));
}

// ---------------- BN stats for prices (input only) ----------------------------
__global__ void stats_kernel(const float* __restrict__ x, size_t t_stride,
                             int row_stride, int D, int rows_per_split) {
    const int t = blockIdx.x, split = blockIdx.y;
    const float* xt = x + (size_t)t * t_stride +
                      (size_t)split * rows_per_split * row_stride;
    for (int d = threadIdx.x; d < D; d += blockDim.x) {
        float s = 0.f, q = 0.f;
        for (int r = 0; r < rows_per_split; r++) {
            float v = xt[(size_t)r * row_stride + d];
            s += v; q = fmaf(v, v, q);
        }
        int n = gridDim.x * D, i = t * D + d;
        g_psum[split * n + i] = s;
        g_psq [split * n + i] = q;
    }
}
__global__ void finalize_kernel(const float* __restrict__ gamma,
                                const float* __restrict__ beta, int n,
                                float invB, int nparts) {
    int i = blockIdx.x * blockDim.x + threadIdx.x;
    if (i >= n) return;
    float s = 0.f, q = 0.f;
    for (int sp = 0; sp < nparts; sp++) {
        s += g_psum[(size_t)sp * n + i];
        q += g_psq [(size_t)sp * n + i];
    }
    float m = s * invB;
    float v = fmaxf(fmaf(-m, m, q * invB), 0.f);
    float sc = gamma[i] * rsqrtf(v + BN_EPS);
    g_s[i] = sc;
    g_c[i] = fmaf(-m, sc, beta[i]);
}

// ---------------- weight prep --------------------------------------------------
__global__ void prep_w(const float* __restrict__ W, __nv_bfloat16* __restrict__ hi,
                       __nv_bfloat16* __restrict__ lo, size_t nq) {
    size_t i = (size_t)blockIdx.x * blockDim.x + threadIdx.x;
    if (i >= nq) return;
    float4 w = ((const float4*)W)[i];
    uint2 hp, lp;
    split4(w.x, w.y, w.z, w.w, hp, lp);
    ((uint2*)hi)[i] = hp;
    ((uint2*)lo)[i] = lp;
}

// ---------------- activation conversion ----------------------------------------
// prices [B,T,P] -> x0 hi/lo [T,B,P], affine only
__global__ void conv_prices(const float* __restrict__ x,
                            __nv_bfloat16* __restrict__ hi,
                            __nv_bfloat16* __restrict__ lo) {
    size_t i = (size_t)blockIdx.x * 256 + threadIdx.x;
    constexpr size_t total = (size_t)TT * BB * PP / 4;
    if (i >= total) return;
    size_t e = i * 4;
    int t = (int)(e / ((size_t)BB * PP));
    int r = (int)(e - (size_t)t * BB * PP);
    int b = r / PP, p = r - (r / PP) * PP;
    float4 xv = *(const float4*)(x + (size_t)b * (TT * PP) + t * PP + p);
    float4 sv = *(const float4*)(g_s + t * PP + p);
    float4 cv = *(const float4*)(g_c + t * PP + p);
    uint2 hp, lp;
    split4(fmaf(xv.x, sv.x, cv.x), fmaf(xv.y, sv.y, cv.y),
           fmaf(xv.z, sv.z, cv.z), fmaf(xv.w, sv.w, cv.w), hp, lp);
    ((uint2*)hi)[i] = hp;
    ((uint2*)lo)[i] = lp;
}
// h [T,B,H] fp32 -> y hi/lo [T,B,H], relu(affine)
__global__ void conv_act(const float* __restrict__ h,
                         __nv_bfloat16* __restrict__ hi,
                         __nv_bfloat16* __restrict__ lo) {
    size_t i = (size_t)blockIdx.x * 256 + threadIdx.x;
    constexpr size_t total = (size_t)TT * BB * HH / 4;
    if (i >= total) return;
    size_t e = i * 4;
    int t = (int)(e / ((size_t)BB * HH));
    int f = (int)(e % HH);
    float4 xv = *(const float4*)(h + e);
    float4 sv = *(const float4*)(g_s + t * HH + f);
    float4 cv = *(const float4*)(g_c + t * HH + f);
    uint2 hp, lp;
    split4(fmaxf(fmaf(xv.x, sv.x, cv.x), 0.f), fmaxf(fmaf(xv.y, sv.y, cv.y), 0.f),
           fmaxf(fmaf(xv.z, sv.z, cv.z), 0.f), fmaxf(fmaf(xv.w, sv.w, cv.w), 0.f),
           hp, lp);
    ((uint2*)hi)[i] = hp;
    ((uint2*)lo)[i] = lp;
}

// ---------------- lean split-bf16 HMMA GEMM -------------------------------------
// out[t,m,n] = sum_k A[t,m,k]*W[t,k,n] + bias[t,n]; A pre-converted hi/lo.
// If STATS: also emit per-m-block column sums / sumsq of out (deterministic).
template <int BN, int KTOT, int NTOT, bool STATS>
__global__ void __launch_bounds__(256)
gemm_mma(const __nv_bfloat16* __restrict__ Ahi,
         const __nv_bfloat16* __restrict__ Alo,
         const __nv_bfloat16* __restrict__ Whi,
         const __nv_bfloat16* __restrict__ Wlo,
         const float* __restrict__ bias,
         float* __restrict__ out, size_t o_t, int o_rs) {
    constexpr int BM = 128, BK = 64;
    constexpr int AROW = BK + 8, WROW = BN + 8;
    constexpr int A_BYTES = BM * AROW * 2, W_BYTES = BK * WROW * 2;
    constexpr int WHO = 2 * A_BYTES, WLO = 2 * A_BYTES + W_BYTES;
    constexpr int STAGE = 2 * A_BYTES + 2 * W_BYTES;
    constexpr int KT = KTOT / BK;
    constexpr int WARPS_M = 2, WARPS_N = 4;
    constexpr int WTM = BM / WARPS_M, WTN = BN / WARPS_N;
    constexpr int MT = WTM / 16, NT = WTN / 8;
    constexpr int SEGS = BN / 8, ASEG = BK / 8;

    extern __shared__ char smem[];
    const uint32_t sb = smem_u32(smem);
    const int tid = threadIdx.x, wid = tid >> 5, lane = tid & 31;
    const int wm = wid / WARPS_N, wn = wid % WARPS_N;
    const int t = blockIdx.z, n0 = blockIdx.x * BN, m0 = blockIdx.y * BM;

    const __nv_bfloat16* AhT = Ahi + (size_t)t * BB * KTOT + (size_t)m0 * KTOT;
    const __nv_bfloat16* AlT = Alo + (size_t)t * BB * KTOT + (size_t)m0 * KTOT;
    const __nv_bfloat16* WhT = Whi + (size_t)t * KTOT * NTOT + n0;
    const __nv_bfloat16* WlT = Wlo + (size_t)t * KTOT * NTOT + n0;

    auto load = [&](int kt, int st) {
        const uint32_t stb = sb + st * STAGE;
        #pragma unroll
        for (int i = tid; i < BM * ASEG; i += 256) {
            int row = i / ASEG, seg = i % ASEG;
            size_t g = (size_t)row * KTOT + kt * BK + seg * 8;
            uint32_t d = stb + row * (AROW * 2) + seg * 16;
            cp16(d, AhT + g);
            cp16(d + A_BYTES, AlT + g);
        }
        #pragma unroll
        for (int i = tid; i < BK * SEGS; i += 256) {
            int row = i / SEGS, seg = i % SEGS;
            size_t g = (size_t)(kt * BK + row) * NTOT + seg * 8;
            uint32_t d = stb + WHO + row * (WROW * 2) + seg * 16;
            cp16(d, WhT + g);
            cp16(d + W_BYTES, WlT + g);
        }
        asm volatile("cp.async.commit_group;" ::: "memory");
    };

    float acc[MT][NT][4];
    #pragma unroll
    for (int i = 0; i < MT; i++)
        #pragma unroll
        for (int j = 0; j < NT; j++)
            #pragma unroll
            for (int k = 0; k < 4; k++) acc[i][j][k] = 0.f;

    load(0, 0);
    const int lrow = lane & 15, lsel = lane >> 4;

    #pragma unroll 1
    for (int kt = 0; kt < KT; kt++) {
        const int st = kt & 1;
        asm volatile("cp.async.wait_group 0;" ::: "memory");
        __syncthreads();
        if (kt + 1 < KT) load(kt + 1, st ^ 1);
        const uint32_t stb = sb + st * STAGE;
        #pragma unroll
        for (int k16 = 0; k16 < 4; k16++) {
            uint32_t ah[MT][4], al[MT][4];
            #pragma unroll
            for (int mt = 0; mt < MT; mt++) {
                uint32_t off = (uint32_t)((wm * WTM + mt * 16 + lrow) * AROW +
                                          k16 * 16 + lsel * 8) * 2;
                ldm_x4(ah[mt], stb + off);
                ldm_x4(al[mt], stb + A_BYTES + off);
            }
            uint32_t bq[NT][2];
            #pragma unroll
            for (int np = 0; np < NT / 2; np++) {
                uint32_t off = (uint32_t)((k16 * 16 + lrow) * WROW + wn * WTN +
                                          np * 16 + lsel * 8) * 2;
                uint32_t r[4];
                ldm_x4t(r, stb + WHO + off);
                bq[2*np][0] = r[0]; bq[2*np][1] = r[1];
                bq[2*np+1][0] = r[2]; bq[2*np+1][1] = r[3];
            }
            #pragma unroll
            for (int mt = 0; mt < MT; mt++)
                #pragma unroll
                for (int nt = 0; nt < NT; nt++) mma_bf16(acc[mt][nt], ah[mt], bq[nt]);
            #pragma unroll
            for (int mt = 0; mt < MT; mt++)
                #pragma unroll
                for (int nt = 0; nt < NT; nt++) mma_bf16(acc[mt][nt], al[mt], bq[nt]);
            #pragma unroll
            for (int np = 0; np < NT / 2; np++) {
                uint32_t off = (uint32_t)((k16 * 16 + lrow) * WROW + wn * WTN +
                                          np * 16 + lsel * 8) * 2;
                uint32_t r[4];
                ldm_x4t(r, stb + WLO + off);
                bq[2*np][0] = r[0]; bq[2*np][1] = r[1];
                bq[2*np+1][0] = r[2]; bq[2*np+1][1] = r[3];
            }
            #pragma unroll
            for (int mt = 0; mt < MT; mt++)
                #pragma unroll
                for (int nt = 0; nt < NT; nt++) mma_bf16(acc[mt][nt], ah[mt], bq[nt]);
        }
    }
    __syncthreads();   // smem reused below for stats

    // ---- epilogue: bias, store, optional column stats ----
    const int r0 = lane >> 2, c0 = (lane & 3) * 2;
    #pragma unroll
    for (int nt = 0; nt < NT; nt++) {
        float2 bv = *(const float2*)(bias + t * NTOT + n0 + wn * WTN + nt * 8 + c0);
        #pragma unroll
        for (int mt = 0; mt < MT; mt++) {
            acc[mt][nt][0] += bv.x; acc[mt][nt][1] += bv.y;
            acc[mt][nt][2] += bv.x; acc[mt][nt][3] += bv.y;
        }
    }
    #pragma unroll
    for (int mt = 0; mt < MT; mt++) {
        #pragma unroll
        for (int nt = 0; nt < NT; nt++) {
            int col = n0 + wn * WTN + nt * 8 + c0;
            int row = m0 + wm * WTM + mt * 16 + r0;
            float* p0 = out + (size_t)t * o_t + (size_t)row * o_rs + col;
            float* p1 = p0 + (size_t)8 * o_rs;
            *(float2*)p0 = make_float2(acc[mt][nt][0], acc[mt][nt][1]);
            *(float2*)p1 = make_float2(acc[mt][nt][2], acc[mt][nt][3]);
        }
    }
    if (STATS) {
        float* sbuf = (float*)smem;   // [2 wm][2 kind][BN]
        #pragma unroll
        for (int nt = 0; nt < NT; nt++) {
            #pragma unroll
            for (int j = 0; j < 2; j++) {
                float s = 0.f, q = 0.f;
                #pragma unroll
                for (int mt = 0; mt < MT; mt++) {
                    float v0 = acc[mt][nt][j], v1 = acc[mt][nt][2 + j];
                    s += v0 + v1;
                    q = fmaf(v0, v0, q); q = fmaf(v1, v1, q);
                }
                #pragma unroll
                for (int msk = 4; msk <= 16; msk <<= 1) {
                    s += __shfl_xor_sync(0xffffffffu, s, msk);
                    q += __shfl_xor_sync(0xffffffffu, q, msk);
                }
                if (r0 == 0) {
                    int col = wn * WTN + nt * 8 + c0 + j;
                    sbuf[(wm * 2 + 0) * BN + col] = s;
                    sbuf[(wm * 2 + 1) * BN + col] = q;
                }
            }
        }
        __syncthreads();
        for (int cix = tid; cix < BN; cix += 256) {
            float ss = sbuf[0 * BN + cix] + sbuf[2 * BN + cix];
            float qq = sbuf[1 * BN + cix] + sbuf[3 * BN + cix];
            size_t pi = (size_t)blockIdx.y * (TT * NTOT) + (size_t)t * NTOT + n0 + cix;
            g_psum[pi] = ss;
            g_psq [pi] = qq;
        }
    }
}

// ---------------- launch --------------------------------------------------------
extern "C" void kernel_launch(void* const* d_in, const int* in_sizes, int n_in,
                              void* d_out, int out_size) {
    (void)in_sizes; (void)n_in; (void)out_size;
    const float* prices = (const float*)d_in[0];
    const float* bn0_g  = (const float*)d_in[1];
    const float* bn0_b  = (const float*)d_in[2];
    const float* W1     = (const float*)d_in[3];
    const float* b1     = (const float*)d_in[4];
    const float* bn1_g  = (const float*)d_in[5];
    const float* bn1_b  = (const float*)d_in[6];
    const float* W2     = (const float*)d_in[7];
    const float* b2     = (const float*)d_in[8];
    const float* bn2_g  = (const float*)d_in[9];
    const float* bn2_b  = (const float*)d_in[10];
    const float* W3     = (const float*)d_in[11];
    const float* b3     = (const float*)d_in[12];
    float* out = (float*)d_out;

    float *hp;
    __nv_bfloat16 *yh, *yl, *w1h, *w1l, *w2h, *w2l, *w3h, *w3l;
    cudaGetSymbolAddress((void**)&hp,  g_h);
    cudaGetSymbolAddress((void**)&yh,  g_yhi);
    cudaGetSymbolAddress((void**)&yl,  g_ylo);
    cudaGetSymbolAddress((void**)&w1h, g_w1hi);
    cudaGetSymbolAddress((void**)&w1l, g_w1lo);
    cudaGetSymbolAddress((void**)&w2h, g_w2hi);
    cudaGetSymbolAddress((void**)&w2l, g_w2lo);
    cudaGetSymbolAddress((void**)&w3h, g_w3hi);
    cudaGetSymbolAddress((void**)&w3l, g_w3lo);

    const float invB = 1.0f / (float)BB;

    auto g1 = gemm_mma<256, 64,  512, true>;
    auto g2 = gemm_mma<256, 512, 512, true>;
    auto g3 = gemm_mma<64,  512, 64,  false>;
    // STAGE: 2*(128*72*2) + 2*(64*(BN+8)*2)
    constexpr int STAGE_256 = 2 * (128 * 72 * 2) + 2 * (64 * 264 * 2);  // 104448
    constexpr int STAGE_64  = 2 * (128 * 72 * 2) + 2 * (64 * 72 * 2);   // 55296
    constexpr int SM1 = 1 * STAGE_256;   // KT=1 -> single stage
    constexpr int SM2 = 2 * STAGE_256;
    constexpr int SM3 = 2 * STAGE_64;
    cudaFuncSetAttribute(g1, cudaFuncAttributeMaxDynamicSharedMemorySize, SM1);
    cudaFuncSetAttribute(g2, cudaFuncAttributeMaxDynamicSharedMemorySize, SM2);
    cudaFuncSetAttribute(g3, cudaFuncAttributeMaxDynamicSharedMemorySize, SM3);

    // weight prep
    prep_w<<<(int)(((size_t)TT*PP*HH/4 + 255)/256), 256>>>(W1, w1h, w1l, (size_t)TT*PP*HH/4);
    prep_w<<<(int)(((size_t)TT*HH*HH/4 + 255)/256), 256>>>(W2, w2h, w2l, (size_t)TT*HH*HH/4);
    prep_w<<<(int)(((size_t)TT*HH*PP/4 + 255)/256), 256>>>(W3, w3h, w3l, (size_t)TT*HH*PP/4);

    // stage 0: stats on prices -> conv to x0 hi/lo [T,B,P]
    stats_kernel<<<dim3(TT, SPLITS0), 64>>>(prices, (size_t)PP, TT * PP, PP,
                                            BB / SPLITS0);
    finalize_kernel<<<(TT * PP + 255) / 256, 256>>>(bn0_g, bn0_b, TT * PP, invB,
                                                    SPLITS0);
    conv_prices<<<(int)(((size_t)TT*BB*PP/4 + 255)/256), 256>>>(prices, yh, yl);

    // gemm1 -> h (fp32) + stats partials
    g1<<<dim3(HH / 256, BB / 128, TT), 256, SM1>>>(
        yh, yl, w1h, w1l, b1, hp, (size_t)BB * HH, HH);
    finalize_kernel<<<(TT * HH + 255) / 256, 256>>>(bn1_g, bn1_b, TT * HH, invB,
                                                    MBLK);
    conv_act<<<(int)(((size_t)TT*BB*HH/4 + 255)/256), 256>>>(hp, yh, yl);

    // gemm2 -> h (fp32, reused) + stats partials
    g2<<<dim3(HH / 256, BB / 128, TT), 256, SM2>>>(
        yh, yl, w2h, w2l, b2, hp, (size_t)BB * HH, HH);
    finalize_kernel<<<(TT * HH + 255) / 256, 256>>>(bn2_g, bn2_b, TT * HH, invB,
                                                    MBLK);
    conv_act<<<(int)(((size_t)TT*BB*HH/4 + 255)/256), 256>>>(hp, yh, yl);

    // gemm3 -> out [B,T,P]
    g3<<<dim3(1, BB / 128, TT), 256, SM3>>>(
        yh, yl, w3h, w3l, b3, out, (size_t)PP, TT * PP);
}

// round 5
// speedup vs baseline: 2.2479x; 1.0625x over previous
#include <cuda_runtime.h>
#include <cuda_bf16.h>
#include <cstdint>

// ============================================================================
// RNN_BN_simple, round 5: HMMA GEMMs with in-prologue BN+split conversion.
//  - GEMM A-prologue: fp32 LDG -> BN affine (+ReLU) -> bf16 hi/lo -> STS.
//    (hi+lo bf16 is the same 4 B/elem as fp32, so a separate conversion pass
//     is pure extra HBM traffic — removed.)
//  - BN batch stats computed in the GEMM epilogue (deterministic partials).
//  - Split-bf16: x*w ~= xh*wh + xh*wl + xl*wh, fp32 accumulation.
// ============================================================================

namespace {
constexpr int BB = 4096, TT = 64, PP = 64, HH = 512;
constexpr float BN_EPS = 1e-3f;
constexpr int SPLITS0 = 32;      // price-stats splits
constexpr int MBLK = BB / 128;   // 32 epilogue partial blocks
}

// ---------------- scratch ----------------------------------------------------
__device__ float g_h[(size_t)TT * BB * HH];           // raw pre-BN h (reused)
__device__ float g_psum[MBLK * TT * HH];
__device__ float g_psq [MBLK * TT * HH];
__device__ float g_s[TT * HH];
__device__ float g_c[TT * HH];
__device__ __align__(16) __nv_bfloat16 g_w1hi[(size_t)TT * PP * HH];
__device__ __align__(16) __nv_bfloat16 g_w1lo[(size_t)TT * PP * HH];
__device__ __align__(16) __nv_bfloat16 g_w2hi[(size_t)TT * HH * HH];
__device__ __align__(16) __nv_bfloat16 g_w2lo[(size_t)TT * HH * HH];
__device__ __align__(16) __nv_bfloat16 g_w3hi[(size_t)TT * HH * PP];
__device__ __align__(16) __nv_bfloat16 g_w3lo[(size_t)TT * HH * PP];

// ---------------- helpers ------------------------------------------------------
__device__ __forceinline__ uint32_t smem_u32(const void* p) {
    uint32_t a;
    asm("{ .reg .u64 t; cvta.to.shared.u64 t, %1; cvt.u32.u64 %0, t; }"
        : "=r"(a) : "l"(p));
    return a;
}
__device__ __forceinline__ void ldm_x4(uint32_t* r, uint32_t addr) {
    asm volatile("ldmatrix.sync.aligned.m8n8.x4.shared.b16 {%0,%1,%2,%3}, [%4];"
                 : "=r"(r[0]), "=r"(r[1]), "=r"(r[2]), "=r"(r[3]) : "r"(addr));
}
__device__ __forceinline__ void ldm_x4t(uint32_t* r, uint32_t addr) {
    asm volatile("ldmatrix.sync.aligned.m8n8.x4.trans.shared.b16 {%0,%1,%2,%3}, [%4];"
                 : "=r"(r[0]), "=r"(r[1]), "=r"(r[2]), "=r"(r[3]) : "r"(addr));
}
__device__ __forceinline__ void mma_bf16(float* c, const uint32_t* a,
                                         const uint32_t* b) {
    asm volatile(
        "mma.sync.aligned.m16n8k16.row.col.f32.bf16.bf16.f32 "
        "{%0,%1,%2,%3}, {%4,%5,%6,%7}, {%8,%9}, {%0,%1,%2,%3};"
        : "+f"(c[0]), "+f"(c[1]), "+f"(c[2]), "+f"(c[3])
        : "r"(a[0]), "r"(a[1]), "r"(a[2]), "r"(a[3]), "r"(b[0]), "r"(b[1]));
}
__device__ __forceinline__ void cp16(uint32_t dst, const void* src) {
    asm volatile("cp.async.cg.shared.global [%0], [%1], 16;"
                 :: "r"(dst), "l"(src));
}
__device__ __forceinline__ unsigned short bfu(__nv_bfloat16 h) {
    __nv_bfloat16_raw r = h; return r.x;
}
__device__ __forceinline__ void split4(float y0, float y1, float y2, float y3,
                                       uint2& hp, uint2& lp) {
    __nv_bfloat16 h0 = __float2bfloat16(y0), h1 = __float2bfloat16(y1);
    __nv_bfloat16 h2 = __float2bfloat16(y2), h3 = __float2bfloat16(y3);
    unsigned short l0 = bfu(__float2bfloat16(y0 - __bfloat162float(h0)));
    unsigned short l1 = bfu(__float2bfloat16(y1 - __bfloat162float(h1)));
    unsigned short l2 = bfu(__float2bfloat16(y2 - __bfloat162float(h2)));
    unsigned short l3 = bfu(__float2bfloat16(y3 - __bfloat162float(h3)));
    hp = make_uint2(bfu(h0) | ((uint32_t)bfu(h1) << 16),
                    bfu(h2) | ((uint32_t)bfu(h3) << 16));
    lp = make_uint2(l0 | ((uint32_t)l1 << 16), l2 | ((uint32_t)l3 << 16));
}

// ---------------- BN stats for prices ------------------------------------------
__global__ void stats_kernel(const float* __restrict__ x, size_t t_stride,
                             int row_stride, int D, int rows_per_split) {
    const int t = blockIdx.x, split = blockIdx.y;
    const float* xt = x + (size_t)t * t_stride +
                      (size_t)split * rows_per_split * row_stride;
    for (int d = threadIdx.x; d < D; d += blockDim.x) {
        float s0 = 0.f, s1 = 0.f, q0 = 0.f, q1 = 0.f;
        #pragma unroll 2
        for (int r = 0; r < rows_per_split; r += 2) {
            float v0 = xt[(size_t)r * row_stride + d];
            float v1 = xt[(size_t)(r + 1) * row_stride + d];
            s0 += v0; q0 = fmaf(v0, v0, q0);
            s1 += v1; q1 = fmaf(v1, v1, q1);
        }
        int n = gridDim.x * D, i = t * D + d;
        g_psum[split * n + i] = s0 + s1;
        g_psq [split * n + i] = q0 + q1;
    }
}
__global__ void finalize_kernel(const float* __restrict__ gamma,
                                const float* __restrict__ beta, int n,
                                float invB, int nparts) {
    int i = blockIdx.x * blockDim.x + threadIdx.x;
    if (i >= n) return;
    float s = 0.f, q = 0.f;
    for (int sp = 0; sp < nparts; sp++) {
        s += g_psum[(size_t)sp * n + i];
        q += g_psq [(size_t)sp * n + i];
    }
    float m = s * invB;
    float v = fmaxf(fmaf(-m, m, q * invB), 0.f);
    float sc = gamma[i] * rsqrtf(v + BN_EPS);
    g_s[i] = sc;
    g_c[i] = fmaf(-m, sc, beta[i]);
}

// ---------------- weight prep --------------------------------------------------
__global__ void prep_w(const float* __restrict__ W, __nv_bfloat16* __restrict__ hi,
                       __nv_bfloat16* __restrict__ lo, size_t nq) {
    size_t i = (size_t)blockIdx.x * blockDim.x + threadIdx.x;
    if (i >= nq) return;
    float4 w = ((const float4*)W)[i];
    uint2 hp, lp;
    split4(w.x, w.y, w.z, w.w, hp, lp);
    ((uint2*)hi)[i] = hp;
    ((uint2*)lo)[i] = lp;
}

// ---------------- HMMA GEMM with in-prologue conversion --------------------------
// out[t,m,n] = sum_k prelu(A[t,m,k]*s+c) * W[t,k,n] + bias[t,n]
template <int BN, int BK, int KTOT, int NTOT, bool RELU, bool STATS>
__global__ void __launch_bounds__(256)
gemm_mma(const float* __restrict__ A, size_t a_t, int a_rs,
         const __nv_bfloat16* __restrict__ Whi,
         const __nv_bfloat16* __restrict__ Wlo,
         const float* __restrict__ bias,
         float* __restrict__ out, size_t o_t, int o_rs) {
    constexpr int BM = 128;
    constexpr int AROW = BK + 8, WROW = BN + 8;
    constexpr int A_BYTES = BM * AROW * 2, W_BYTES = BK * WROW * 2;
    constexpr int WHO = 2 * A_BYTES, WLP = 2 * A_BYTES + W_BYTES;
    constexpr int STAGE = 2 * A_BYTES + 2 * W_BYTES;
    constexpr int KT = KTOT / BK;
    constexpr int WARPS_M = 2, WARPS_N = 4;
    constexpr int WTM = BM / WARPS_M, WTN = BN / WARPS_N;
    constexpr int MT = WTM / 16, NT = WTN / 8;
    constexpr int SEGS = BN / 8;
    constexpr int AV = BM * BK / (4 * 256);
    constexpr int KQL = BK / 4;          // float4 columns per A row
    constexpr int RPV = 256 / KQL;       // A rows per vector step

    extern __shared__ char smem[];
    const uint32_t sb = smem_u32(smem);
    const int tid = threadIdx.x, wid = tid >> 5, lane = tid & 31;
    const int wm = wid / WARPS_N, wn = wid % WARPS_N;
    const int t = blockIdx.z, n0 = blockIdx.x * BN, m0 = blockIdx.y * BM;

    const int kq = tid % KQL, rowb = tid / KQL;
    const float* At = A + (size_t)t * a_t + (size_t)m0 * a_rs;
    const float* sArr = g_s + t * KTOT;
    const float* cArr = g_c + t * KTOT;
    const __nv_bfloat16* WhT = Whi + (size_t)t * KTOT * NTOT + n0;
    const __nv_bfloat16* WlT = Wlo + (size_t)t * KTOT * NTOT + n0;

    float4 areg[AV];
    float4 sv, cv;
    auto ldgA = [&](int kt) {
        const float* base = At + kt * BK + kq * 4;
        #pragma unroll
        for (int v = 0; v < AV; v++)
            areg[v] = *(const float4*)(base + (size_t)(rowb + v * RPV) * a_rs);
        sv = *(const float4*)(sArr + kt * BK + kq * 4);
        cv = *(const float4*)(cArr + kt * BK + kq * 4);
    };
    auto stsA = [&](int st) {
        char* hb = smem + st * STAGE;
        #pragma unroll
        for (int v = 0; v < AV; v++) {
            float y0 = fmaf(areg[v].x, sv.x, cv.x);
            float y1 = fmaf(areg[v].y, sv.y, cv.y);
            float y2 = fmaf(areg[v].z, sv.z, cv.z);
            float y3 = fmaf(areg[v].w, sv.w, cv.w);
            if (RELU) {
                y0 = fmaxf(y0, 0.f); y1 = fmaxf(y1, 0.f);
                y2 = fmaxf(y2, 0.f); y3 = fmaxf(y3, 0.f);
            }
            uint2 hp, lp;
            split4(y0, y1, y2, y3, hp, lp);
            uint32_t off = (uint32_t)((rowb + v * RPV) * AROW + kq * 4) * 2;
            *(uint2*)(hb + off) = hp;
            *(uint2*)(hb + A_BYTES + off) = lp;
        }
    };
    auto cpW = [&](int kt, int st) {
        const uint32_t stb = sb + st * STAGE;
        #pragma unroll
        for (int i = tid; i < BK * SEGS; i += 256) {
            int row = i / SEGS, seg = i % SEGS;
            size_t g = (size_t)(kt * BK + row) * NTOT + seg * 8;
            uint32_t d = stb + WHO + row * (WROW * 2) + seg * 16;
            cp16(d, WhT + g);
            cp16(d + W_BYTES, WlT + g);
        }
        asm volatile("cp.async.commit_group;" ::: "memory");
    };

    float acc[MT][NT][4];
    #pragma unroll
    for (int i = 0; i < MT; i++)
        #pragma unroll
        for (int j = 0; j < NT; j++)
            #pragma unroll
            for (int k = 0; k < 4; k++) acc[i][j][k] = 0.f;

    ldgA(0);
    cpW(0, 0);
    stsA(0);
    const int lrow = lane & 15, lsel = lane >> 4;

    #pragma unroll 1
    for (int kt = 0; kt < KT; kt++) {
        const int st = kt & 1;
        asm volatile("cp.async.wait_group 0;" ::: "memory");
        __syncthreads();
        if (kt + 1 < KT) { ldgA(kt + 1); cpW(kt + 1, st ^ 1); }
        const uint32_t stb = sb + st * STAGE;
        #pragma unroll
        for (int k16 = 0; k16 < BK / 16; k16++) {
            uint32_t ah[MT][4], al[MT][4];
            #pragma unroll
            for (int mt = 0; mt < MT; mt++) {
                uint32_t off = (uint32_t)((wm * WTM + mt * 16 + lrow) * AROW +
                                          k16 * 16 + lsel * 8) * 2;
                ldm_x4(ah[mt], stb + off);
                ldm_x4(al[mt], stb + A_BYTES + off);
            }
            uint32_t bq[NT][2];
            #pragma unroll
            for (int np = 0; np < NT / 2; np++) {
                uint32_t off = (uint32_t)((k16 * 16 + lrow) * WROW + wn * WTN +
                                          np * 16 + lsel * 8) * 2;
                uint32_t r[4];
                ldm_x4t(r, stb + WHO + off);
                bq[2*np][0] = r[0]; bq[2*np][1] = r[1];
                bq[2*np+1][0] = r[2]; bq[2*np+1][1] = r[3];
            }
            #pragma unroll
            for (int mt = 0; mt < MT; mt++)
                #pragma unroll
                for (int nt = 0; nt < NT; nt++) mma_bf16(acc[mt][nt], ah[mt], bq[nt]);
            #pragma unroll
            for (int mt = 0; mt < MT; mt++)
                #pragma unroll
                for (int nt = 0; nt < NT; nt++) mma_bf16(acc[mt][nt], al[mt], bq[nt]);
            #pragma unroll
            for (int np = 0; np < NT / 2; np++) {
                uint32_t off = (uint32_t)((k16 * 16 + lrow) * WROW + wn * WTN +
                                          np * 16 + lsel * 8) * 2;
                uint32_t r[4];
                ldm_x4t(r, stb + WLP + off);
                bq[2*np][0] = r[0]; bq[2*np][1] = r[1];
                bq[2*np+1][0] = r[2]; bq[2*np+1][1] = r[3];
            }
            #pragma unroll
            for (int mt = 0; mt < MT; mt++)
                #pragma unroll
                for (int nt = 0; nt < NT; nt++) mma_bf16(acc[mt][nt], ah[mt], bq[nt]);
        }
        if (kt + 1 < KT) stsA(st ^ 1);
    }
    __syncthreads();   // smem reused below for stats

    // ---- epilogue: bias, store, optional column stats ----
    const int r0 = lane >> 2, c0 = (lane & 3) * 2;
    #pragma unroll
    for (int nt = 0; nt < NT; nt++) {
        float2 bv = *(const float2*)(bias + t * NTOT + n0 + wn * WTN + nt * 8 + c0);
        #pragma unroll
        for (int mt = 0; mt < MT; mt++) {
            acc[mt][nt][0] += bv.x; acc[mt][nt][1] += bv.y;
            acc[mt][nt][2] += bv.x; acc[mt][nt][3] += bv.y;
        }
    }
    #pragma unroll
    for (int mt = 0; mt < MT; mt++) {
        #pragma unroll
        for (int nt = 0; nt < NT; nt++) {
            int col = n0 + wn * WTN + nt * 8 + c0;
            int row = m0 + wm * WTM + mt * 16 + r0;
            float* p0 = out + (size_t)t * o_t + (size_t)row * o_rs + col;
            float* p1 = p0 + (size_t)8 * o_rs;
            *(float2*)p0 = make_float2(acc[mt][nt][0], acc[mt][nt][1]);
            *(float2*)p1 = make_float2(acc[mt][nt][2], acc[mt][nt][3]);
        }
    }
    if (STATS) {
        float* sbuf = (float*)smem;   // [2 wm][2 kind][BN]
        #pragma unroll
        for (int nt = 0; nt < NT; nt++) {
            #pragma unroll
            for (int j = 0; j < 2; j++) {
                float s = 0.f, q = 0.f;
                #pragma unroll
                for (int mt = 0; mt < MT; mt++) {
                    float v0 = acc[mt][nt][j], v1 = acc[mt][nt][2 + j];
                    s += v0 + v1;
                    q = fmaf(v0, v0, q); q = fmaf(v1, v1, q);
                }
                #pragma unroll
                for (int msk = 4; msk <= 16; msk <<= 1) {
                    s += __shfl_xor_sync(0xffffffffu, s, msk);
                    q += __shfl_xor_sync(0xffffffffu, q, msk);
                }
                if (r0 == 0) {
                    int col = wn * WTN + nt * 8 + c0 + j;
                    sbuf[(wm * 2 + 0) * BN + col] = s;
                    sbuf[(wm * 2 + 1) * BN + col] = q;
                }
            }
        }
        __syncthreads();
        for (int cix = tid; cix < BN; cix += 256) {
            float ss = sbuf[0 * BN + cix] + sbuf[2 * BN + cix];
            float qq = sbuf[1 * BN + cix] + sbuf[3 * BN + cix];
            size_t pi = (size_t)blockIdx.y * (TT * NTOT) + (size_t)t * NTOT + n0 + cix;
            g_psum[pi] = ss;
            g_psq [pi] = qq;
        }
    }
}

// ---------------- launch --------------------------------------------------------
extern "C" void kernel_launch(void* const* d_in, const int* in_sizes, int n_in,
                              void* d_out, int out_size) {
    (void)in_sizes; (void)n_in; (void)out_size;
    const float* prices = (const float*)d_in[0];
    const float* bn0_g  = (const float*)d_in[1];
    const float* bn0_b  = (const float*)d_in[2];
    const float* W1     = (const float*)d_in[3];
    const float* b1     = (const float*)d_in[4];
    const float* bn1_g  = (const float*)d_in[5];
    const float* bn1_b  = (const float*)d_in[6];
    const float* W2     = (const float*)d_in[7];
    const float* b2     = (const float*)d_in[8];
    const float* bn2_g  = (const float*)d_in[9];
    const float* bn2_b  = (const float*)d_in[10];
    const float* W3     = (const float*)d_in[11];
    const float* b3     = (const float*)d_in[12];
    float* out = (float*)d_out;

    float* hp;
    __nv_bfloat16 *w1h, *w1l, *w2h, *w2l, *w3h, *w3l;
    cudaGetSymbolAddress((void**)&hp,  g_h);
    cudaGetSymbolAddress((void**)&w1h, g_w1hi);
    cudaGetSymbolAddress((void**)&w1l, g_w1lo);
    cudaGetSymbolAddress((void**)&w2h, g_w2hi);
    cudaGetSymbolAddress((void**)&w2l, g_w2lo);
    cudaGetSymbolAddress((void**)&w3h, g_w3hi);
    cudaGetSymbolAddress((void**)&w3l, g_w3lo);

    const float invB = 1.0f / (float)BB;

    auto g1 = gemm_mma<256, 64, 64,  512, false, true>;
    auto g2 = gemm_mma<256, 64, 512, 512, true,  true>;
    auto g3 = gemm_mma<64,  64, 512, 64,  true,  false>;
    constexpr int STAGE_256 = 2 * (128 * 72 * 2) + 2 * (64 * 264 * 2);  // 104448
    constexpr int STAGE_64  = 2 * (128 * 72 * 2) + 2 * (64 * 72 * 2);   // 55296
    constexpr int SM1 = 1 * STAGE_256;
    constexpr int SM2 = 2 * STAGE_256;
    constexpr int SM3 = 2 * STAGE_64;
    cudaFuncSetAttribute(g1, cudaFuncAttributeMaxDynamicSharedMemorySize, SM1);
    cudaFuncSetAttribute(g2, cudaFuncAttributeMaxDynamicSharedMemorySize, SM2);
    cudaFuncSetAttribute(g3, cudaFuncAttributeMaxDynamicSharedMemorySize, SM3);

    // weight prep
    prep_w<<<(int)(((size_t)TT*PP*HH/4 + 255)/256), 256>>>(W1, w1h, w1l, (size_t)TT*PP*HH/4);
    prep_w<<<(int)(((size_t)TT*HH*HH/4 + 255)/256), 256>>>(W2, w2h, w2l, (size_t)TT*HH*HH/4);
    prep_w<<<(int)(((size_t)TT*HH*PP/4 + 255)/256), 256>>>(W3, w3h, w3l, (size_t)TT*HH*PP/4);

    // BN0 stats on prices
    stats_kernel<<<dim3(TT, SPLITS0), 64>>>(prices, (size_t)PP, TT * PP, PP,
                                            BB / SPLITS0);
    finalize_kernel<<<(TT * PP + 255) / 256, 256>>>(bn0_g, bn0_b, TT * PP, invB,
                                                    SPLITS0);

    // gemm1: h = bn0(prices) @ W1 + b1, stats partials for BN1
    g1<<<dim3(HH / 256, BB / 128, TT), 256, SM1>>>(
        prices, (size_t)PP, TT * PP, w1h, w1l, b1, hp, (size_t)BB * HH, HH);
    finalize_kernel<<<(TT * HH + 255) / 256, 256>>>(bn1_g, bn1_b, TT * HH, invB,
                                                    MBLK);

    // gemm2: h = relu(bn1(h)) @ W2 + b2, stats partials for BN2
    g2<<<dim3(HH / 256, BB / 128, TT), 256, SM2>>>(
        hp, (size_t)BB * HH, HH, w2h, w2l, b2, hp, (size_t)BB * HH, HH);
    finalize_kernel<<<(TT * HH + 255) / 256, 256>>>(bn2_g, bn2_b, TT * HH, invB,
                                                    MBLK);

    // gemm3: out = relu(bn2(h)) @ W3 + b3
    g3<<<dim3(1, BB / 128, TT), 256, SM3>>>(
        hp, (size_t)BB * HH, HH, w3h, w3l, b3, out, (size_t)PP, TT * PP);
}

// round 6
// speedup vs baseline: 2.3744x; 1.0563x over previous
#include <cuda_runtime.h>
#include <cuda_bf16.h>
#include <cstdint>

// ============================================================================
// RNN_BN_simple, round 6: HMMA GEMMs, conversion fully overlapped.
//  - A-prologue (fp32 LDG -> BN affine (+ReLU) -> bf16 hi/lo -> STS) is issued
//    between the first and remaining k16 sub-chunks, so it hides under HMMA
//    instead of sitting on the barrier critical path (round-5 mistake).
//  - Truncation-based hi/lo split: PRMT for hi-pack, exact fp32 remainder,
//    cvt.rn.bf16x2 for lo-pack.
//  - Split-bf16: x*w ~= xh*wh + xh*wl + xl*wh, fp32 accumulation.
// ============================================================================

namespace {
constexpr int BB = 4096, TT = 64, PP = 64, HH = 512;
constexpr float BN_EPS = 1e-3f;
constexpr int SPLITS0 = 32;
constexpr int MBLK = BB / 128;
}

// ---------------- scratch ----------------------------------------------------
__device__ float g_h[(size_t)TT * BB * HH];
__device__ float g_psum[MBLK * TT * HH];
__device__ float g_psq [MBLK * TT * HH];
__device__ float g_s[TT * HH];
__device__ float g_c[TT * HH];
__device__ __align__(16) __nv_bfloat16 g_w1hi[(size_t)TT * PP * HH];
__device__ __align__(16) __nv_bfloat16 g_w1lo[(size_t)TT * PP * HH];
__device__ __align__(16) __nv_bfloat16 g_w2hi[(size_t)TT * HH * HH];
__device__ __align__(16) __nv_bfloat16 g_w2lo[(size_t)TT * HH * HH];
__device__ __align__(16) __nv_bfloat16 g_w3hi[(size_t)TT * HH * PP];
__device__ __align__(16) __nv_bfloat16 g_w3lo[(size_t)TT * HH * PP];

// ---------------- helpers ------------------------------------------------------
__device__ __forceinline__ uint32_t smem_u32(const void* p) {
    uint32_t a;
    asm("{ .reg .u64 t; cvta.to.shared.u64 t, %1; cvt.u32.u64 %0, t; }"
        : "=r"(a) : "l"(p));
    return a;
}
__device__ __forceinline__ void ldm_x4(uint32_t* r, uint32_t addr) {
    asm volatile("ldmatrix.sync.aligned.m8n8.x4.shared.b16 {%0,%1,%2,%3}, [%4];"
                 : "=r"(r[0]), "=r"(r[1]), "=r"(r[2]), "=r"(r[3]) : "r"(addr));
}
__device__ __forceinline__ void ldm_x4t(uint32_t* r, uint32_t addr) {
    asm volatile("ldmatrix.sync.aligned.m8n8.x4.trans.shared.b16 {%0,%1,%2,%3}, [%4];"
                 : "=r"(r[0]), "=r"(r[1]), "=r"(r[2]), "=r"(r[3]) : "r"(addr));
}
__device__ __forceinline__ void mma_bf16(float* c, const uint32_t* a,
                                         const uint32_t* b) {
    asm volatile(
        "mma.sync.aligned.m16n8k16.row.col.f32.bf16.bf16.f32 "
        "{%0,%1,%2,%3}, {%4,%5,%6,%7}, {%8,%9}, {%0,%1,%2,%3};"
        : "+f"(c[0]), "+f"(c[1]), "+f"(c[2]), "+f"(c[3])
        : "r"(a[0]), "r"(a[1]), "r"(a[2]), "r"(a[3]), "r"(b[0]), "r"(b[1]));
}
__device__ __forceinline__ void cp16(uint32_t dst, const void* src) {
    asm volatile("cp.async.cg.shared.global [%0], [%1], 16;"
                 :: "r"(dst), "l"(src));
}
__device__ __forceinline__ uint32_t prmt_hi(uint32_t a, uint32_t b) {
    uint32_t d;
    asm("prmt.b32 %0, %1, %2, 0x7632;" : "=r"(d) : "r"(a), "r"(b));
    return d;
}
__device__ __forceinline__ uint32_t cvt_bf16x2(float hi_elem, float lo_elem) {
    uint32_t d;
    asm("cvt.rn.bf16x2.f32 %0, %1, %2;" : "=r"(d) : "f"(hi_elem), "f"(lo_elem));
    return d;
}
// truncation split: hp = packed top-16 bits; lp = rn(y - trunc(y)) packed
__device__ __forceinline__ void split4(float y0, float y1, float y2, float y3,
                                       uint2& hp, uint2& lp) {
    uint32_t b0 = __float_as_uint(y0), b1 = __float_as_uint(y1);
    uint32_t b2 = __float_as_uint(y2), b3 = __float_as_uint(y3);
    hp.x = prmt_hi(b0, b1);
    hp.y = prmt_hi(b2, b3);
    float l0 = y0 - __uint_as_float(b0 & 0xFFFF0000u);
    float l1 = y1 - __uint_as_float(b1 & 0xFFFF0000u);
    float l2 = y2 - __uint_as_float(b2 & 0xFFFF0000u);
    float l3 = y3 - __uint_as_float(b3 & 0xFFFF0000u);
    lp.x = cvt_bf16x2(l1, l0);
    lp.y = cvt_bf16x2(l3, l2);
}

// ---------------- BN stats for prices ------------------------------------------
__global__ void stats_kernel(const float* __restrict__ x, size_t t_stride,
                             int row_stride, int D, int rows_per_split) {
    const int t = blockIdx.x, split = blockIdx.y;
    const float* xt = x + (size_t)t * t_stride +
                      (size_t)split * rows_per_split * row_stride;
    for (int d = threadIdx.x; d < D; d += blockDim.x) {
        float s0 = 0.f, s1 = 0.f, q0 = 0.f, q1 = 0.f;
        #pragma unroll 2
        for (int r = 0; r < rows_per_split; r += 2) {
            float v0 = xt[(size_t)r * row_stride + d];
            float v1 = xt[(size_t)(r + 1) * row_stride + d];
            s0 += v0; q0 = fmaf(v0, v0, q0);
            s1 += v1; q1 = fmaf(v1, v1, q1);
        }
        int n = gridDim.x * D, i = t * D + d;
        g_psum[split * n + i] = s0 + s1;
        g_psq [split * n + i] = q0 + q1;
    }
}
__global__ void finalize_kernel(const float* __restrict__ gamma,
                                const float* __restrict__ beta, int n,
                                float invB, int nparts) {
    int i = blockIdx.x * blockDim.x + threadIdx.x;
    if (i >= n) return;
    float s = 0.f, q = 0.f;
    for (int sp = 0; sp < nparts; sp++) {
        s += g_psum[(size_t)sp * n + i];
        q += g_psq [(size_t)sp * n + i];
    }
    float m = s * invB;
    float v = fmaxf(fmaf(-m, m, q * invB), 0.f);
    float sc = gamma[i] * rsqrtf(v + BN_EPS);
    g_s[i] = sc;
    g_c[i] = fmaf(-m, sc, beta[i]);
}

// ---------------- weight prep --------------------------------------------------
__global__ void prep_w(const float* __restrict__ W, __nv_bfloat16* __restrict__ hi,
                       __nv_bfloat16* __restrict__ lo, size_t nq) {
    size_t i = (size_t)blockIdx.x * blockDim.x + threadIdx.x;
    if (i >= nq) return;
    float4 w = ((const float4*)W)[i];
    uint2 hp, lp;
    split4(w.x, w.y, w.z, w.w, hp, lp);
    ((uint2*)hi)[i] = hp;
    ((uint2*)lo)[i] = lp;
}

// ---------------- HMMA GEMM with overlapped in-prologue conversion ----------------
template <int BN, int BK, int KTOT, int NTOT, bool RELU, bool STATS>
__global__ void __launch_bounds__(256)
gemm_mma(const float* __restrict__ A, size_t a_t, int a_rs,
         const __nv_bfloat16* __restrict__ Whi,
         const __nv_bfloat16* __restrict__ Wlo,
         const float* __restrict__ bias,
         float* __restrict__ out, size_t o_t, int o_rs) {
    constexpr int BM = 128;
    constexpr int AROW = BK + 8, WROW = BN + 8;
    constexpr int A_BYTES = BM * AROW * 2, W_BYTES = BK * WROW * 2;
    constexpr int WHO = 2 * A_BYTES, WLP = 2 * A_BYTES + W_BYTES;
    constexpr int STAGE = 2 * A_BYTES + 2 * W_BYTES;
    constexpr int KT = KTOT / BK;
    constexpr int WARPS_M = 2, WARPS_N = 4;
    constexpr int WTM = BM / WARPS_M, WTN = BN / WARPS_N;
    constexpr int MT = WTM / 16, NT = WTN / 8;
    constexpr int SEGS = BN / 8;
    constexpr int AV = BM * BK / (4 * 256);
    constexpr int KQL = BK / 4;
    constexpr int RPV = 256 / KQL;
    constexpr int NK16 = BK / 16;

    extern __shared__ char smem[];
    const uint32_t sb = smem_u32(smem);
    const int tid = threadIdx.x, wid = tid >> 5, lane = tid & 31;
    const int wm = wid / WARPS_N, wn = wid % WARPS_N;
    const int t = blockIdx.z, n0 = blockIdx.x * BN, m0 = blockIdx.y * BM;

    const int kq = tid % KQL, rowb = tid / KQL;
    const float* At = A + (size_t)t * a_t + (size_t)m0 * a_rs;
    const float* sArr = g_s + t * KTOT;
    const float* cArr = g_c + t * KTOT;
    const __nv_bfloat16* WhT = Whi + (size_t)t * KTOT * NTOT + n0;
    const __nv_bfloat16* WlT = Wlo + (size_t)t * KTOT * NTOT + n0;

    float4 areg[AV];
    float4 sv, cv;
    auto ldgA = [&](int kt) {
        const float* base = At + kt * BK + kq * 4;
        #pragma unroll
        for (int v = 0; v < AV; v++)
            areg[v] = *(const float4*)(base + (size_t)(rowb + v * RPV) * a_rs);
        sv = *(const float4*)(sArr + kt * BK + kq * 4);
        cv = *(const float4*)(cArr + kt * BK + kq * 4);
    };
    auto stsA = [&](int st) {
        char* hb = smem + st * STAGE;
        #pragma unroll
        for (int v = 0; v < AV; v++) {
            float y0 = fmaf(areg[v].x, sv.x, cv.x);
            float y1 = fmaf(areg[v].y, sv.y, cv.y);
            float y2 = fmaf(areg[v].z, sv.z, cv.z);
            float y3 = fmaf(areg[v].w, sv.w, cv.w);
            if (RELU) {
                y0 = fmaxf(y0, 0.f); y1 = fmaxf(y1, 0.f);
                y2 = fmaxf(y2, 0.f); y3 = fmaxf(y3, 0.f);
            }
            uint2 hp, lp;
            split4(y0, y1, y2, y3, hp, lp);
            uint32_t off = (uint32_t)((rowb + v * RPV) * AROW + kq * 4) * 2;
            *(uint2*)(hb + off) = hp;
            *(uint2*)(hb + A_BYTES + off) = lp;
        }
    };
    auto cpW = [&](int kt, int st) {
        const uint32_t stb = sb + st * STAGE;
        #pragma unroll
        for (int i = tid; i < BK * SEGS; i += 256) {
            int row = i / SEGS, seg = i % SEGS;
            size_t g = (size_t)(kt * BK + row) * NTOT + seg * 8;
            uint32_t d = stb + WHO + row * (WROW * 2) + seg * 16;
            cp16(d, WhT + g);
            cp16(d + W_BYTES, WlT + g);
        }
        asm volatile("cp.async.commit_group;" ::: "memory");
    };

    float acc[MT][NT][4];
    #pragma unroll
    for (int i = 0; i < MT; i++)
        #pragma unroll
        for (int j = 0; j < NT; j++)
            #pragma unroll
            for (int k = 0; k < 4; k++) acc[i][j][k] = 0.f;

    const int lrow = lane & 15, lsel = lane >> 4;

    auto compute_k16 = [&](uint32_t stb, int k16) {
        uint32_t ah[MT][4], al[MT][4];
        #pragma unroll
        for (int mt = 0; mt < MT; mt++) {
            uint32_t off = (uint32_t)((wm * WTM + mt * 16 + lrow) * AROW +
                                      k16 * 16 + lsel * 8) * 2;
            ldm_x4(ah[mt], stb + off);
            ldm_x4(al[mt], stb + A_BYTES + off);
        }
        uint32_t bq[NT][2];
        #pragma unroll
        for (int np = 0; np < NT / 2; np++) {
            uint32_t off = (uint32_t)((k16 * 16 + lrow) * WROW + wn * WTN +
                                      np * 16 + lsel * 8) * 2;
            uint32_t r[4];
            ldm_x4t(r, stb + WHO + off);
            bq[2*np][0] = r[0]; bq[2*np][1] = r[1];
            bq[2*np+1][0] = r[2]; bq[2*np+1][1] = r[3];
        }
        #pragma unroll
        for (int mt = 0; mt < MT; mt++)
            #pragma unroll
            for (int nt = 0; nt < NT; nt++) mma_bf16(acc[mt][nt], ah[mt], bq[nt]);
        #pragma unroll
        for (int mt = 0; mt < MT; mt++)
            #pragma unroll
            for (int nt = 0; nt < NT; nt++) mma_bf16(acc[mt][nt], al[mt], bq[nt]);
        #pragma unroll
        for (int np = 0; np < NT / 2; np++) {
            uint32_t off = (uint32_t)((k16 * 16 + lrow) * WROW + wn * WTN +
                                      np * 16 + lsel * 8) * 2;
            uint32_t r[4];
            ldm_x4t(r, stb + WLP + off);
            bq[2*np][0] = r[0]; bq[2*np][1] = r[1];
            bq[2*np+1][0] = r[2]; bq[2*np+1][1] = r[3];
        }
        #pragma unroll
        for (int mt = 0; mt < MT; mt++)
            #pragma unroll
            for (int nt = 0; nt < NT; nt++) mma_bf16(acc[mt][nt], ah[mt], bq[nt]);
    };

    // prologue
    ldgA(0);
    cpW(0, 0);
    stsA(0);

    #pragma unroll 1
    for (int kt = 0; kt < KT; kt++) {
        const int st = kt & 1;
        asm volatile("cp.async.wait_group 0;" ::: "memory");
        __syncthreads();
        const bool more = (kt + 1 < KT);
        if (more) { cpW(kt + 1, st ^ 1); ldgA(kt + 1); }
        const uint32_t stb = sb + st * STAGE;
        compute_k16(stb, 0);
        if (more) stsA(st ^ 1);      // overlapped: writes the other stage
        #pragma unroll
        for (int k16 = 1; k16 < NK16; k16++) compute_k16(stb, k16);
    }
    __syncthreads();   // smem reused below for stats

    // ---- epilogue: bias, store, optional column stats ----
    const int r0 = lane >> 2, c0 = (lane & 3) * 2;
    #pragma unroll
    for (int nt = 0; nt < NT; nt++) {
        float2 bv = *(const float2*)(bias + t * NTOT + n0 + wn * WTN + nt * 8 + c0);
        #pragma unroll
        for (int mt = 0; mt < MT; mt++) {
            acc[mt][nt][0] += bv.x; acc[mt][nt][1] += bv.y;
            acc[mt][nt][2] += bv.x; acc[mt][nt][3] += bv.y;
        }
    }
    #pragma unroll
    for (int mt = 0; mt < MT; mt++) {
        #pragma unroll
        for (int nt = 0; nt < NT; nt++) {
            int col = n0 + wn * WTN + nt * 8 + c0;
            int row = m0 + wm * WTM + mt * 16 + r0;
            float* p0 = out + (size_t)t * o_t + (size_t)row * o_rs + col;
            float* p1 = p0 + (size_t)8 * o_rs;
            *(float2*)p0 = make_float2(acc[mt][nt][0], acc[mt][nt][1]);
            *(float2*)p1 = make_float2(acc[mt][nt][2], acc[mt][nt][3]);
        }
    }
    if (STATS) {
        float* sbuf = (float*)smem;   // [2 wm][2 kind][BN]
        #pragma unroll
        for (int nt = 0; nt < NT; nt++) {
            #pragma unroll
            for (int j = 0; j < 2; j++) {
                float s = 0.f, q = 0.f;
                #pragma unroll
                for (int mt = 0; mt < MT; mt++) {
                    float v0 = acc[mt][nt][j], v1 = acc[mt][nt][2 + j];
                    s += v0 + v1;
                    q = fmaf(v0, v0, q); q = fmaf(v1, v1, q);
                }
                #pragma unroll
                for (int msk = 4; msk <= 16; msk <<= 1) {
                    s += __shfl_xor_sync(0xffffffffu, s, msk);
                    q += __shfl_xor_sync(0xffffffffu, q, msk);
                }
                if (r0 == 0) {
                    int col = wn * WTN + nt * 8 + c0 + j;
                    sbuf[(wm * 2 + 0) * BN + col] = s;
                    sbuf[(wm * 2 + 1) * BN + col] = q;
                }
            }
        }
        __syncthreads();
        for (int cix = tid; cix < BN; cix += 256) {
            float ss = sbuf[0 * BN + cix] + sbuf[2 * BN + cix];
            float qq = sbuf[1 * BN + cix] + sbuf[3 * BN + cix];
            size_t pi = (size_t)blockIdx.y * (TT * NTOT) + (size_t)t * NTOT + n0 + cix;
            g_psum[pi] = ss;
            g_psq [pi] = qq;
        }
    }
}

// ---------------- launch --------------------------------------------------------
extern "C" void kernel_launch(void* const* d_in, const int* in_sizes, int n_in,
                              void* d_out, int out_size) {
    (void)in_sizes; (void)n_in; (void)out_size;
    const float* prices = (const float*)d_in[0];
    const float* bn0_g  = (const float*)d_in[1];
    const float* bn0_b  = (const float*)d_in[2];
    const float* W1     = (const float*)d_in[3];
    const float* b1     = (const float*)d_in[4];
    const float* bn1_g  = (const float*)d_in[5];
    const float* bn1_b  = (const float*)d_in[6];
    const float* W2     = (const float*)d_in[7];
    const float* b2     = (const float*)d_in[8];
    const float* bn2_g  = (const float*)d_in[9];
    const float* bn2_b  = (const float*)d_in[10];
    const float* W3     = (const float*)d_in[11];
    const float* b3     = (const float*)d_in[12];
    float* out = (float*)d_out;

    float* hp;
    __nv_bfloat16 *w1h, *w1l, *w2h, *w2l, *w3h, *w3l;
    cudaGetSymbolAddress((void**)&hp,  g_h);
    cudaGetSymbolAddress((void**)&w1h, g_w1hi);
    cudaGetSymbolAddress((void**)&w1l, g_w1lo);
    cudaGetSymbolAddress((void**)&w2h, g_w2hi);
    cudaGetSymbolAddress((void**)&w2l, g_w2lo);
    cudaGetSymbolAddress((void**)&w3h, g_w3hi);
    cudaGetSymbolAddress((void**)&w3l, g_w3lo);

    const float invB = 1.0f / (float)BB;

    auto g1 = gemm_mma<256, 64, 64,  512, false, true>;
    auto g2 = gemm_mma<256, 64, 512, 512, true,  true>;
    auto g3 = gemm_mma<64,  64, 512, 64,  true,  false>;
    constexpr int STAGE_256 = 2 * (128 * 72 * 2) + 2 * (64 * 264 * 2);  // 104448
    constexpr int STAGE_64  = 2 * (128 * 72 * 2) + 2 * (64 * 72 * 2);   // 55296
    constexpr int SM1 = 1 * STAGE_256;
    constexpr int SM2 = 2 * STAGE_256;
    constexpr int SM3 = 2 * STAGE_64;
    cudaFuncSetAttribute(g1, cudaFuncAttributeMaxDynamicSharedMemorySize, SM1);
    cudaFuncSetAttribute(g2, cudaFuncAttributeMaxDynamicSharedMemorySize, SM2);
    cudaFuncSetAttribute(g3, cudaFuncAttributeMaxDynamicSharedMemorySize, SM3);

    // weight prep
    prep_w<<<(int)(((size_t)TT*PP*HH/4 + 255)/256), 256>>>(W1, w1h, w1l, (size_t)TT*PP*HH/4);
    prep_w<<<(int)(((size_t)TT*HH*HH/4 + 255)/256), 256>>>(W2, w2h, w2l, (size_t)TT*HH*HH/4);
    prep_w<<<(int)(((size_t)TT*HH*PP/4 + 255)/256), 256>>>(W3, w3h, w3l, (size_t)TT*HH*PP/4);

    // BN0 stats on prices
    stats_kernel<<<dim3(TT, SPLITS0), 64>>>(prices, (size_t)PP, TT * PP, PP,
                                            BB / SPLITS0);
    finalize_kernel<<<(TT * PP + 255) / 256, 256>>>(bn0_g, bn0_b, TT * PP, invB,
                                                    SPLITS0);

    // gemm1: h = bn0(prices) @ W1 + b1, stats partials for BN1
    g1<<<dim3(HH / 256, BB / 128, TT), 256, SM1>>>(
        prices, (size_t)PP, TT * PP, w1h, w1l, b1, hp, (size_t)BB * HH, HH);
    finalize_kernel<<<(TT * HH + 255) / 256, 256>>>(bn1_g, bn1_b, TT * HH, invB,
                                                    MBLK);

    // gemm2: h = relu(bn1(h)) @ W2 + b2, stats partials for BN2
    g2<<<dim3(HH / 256, BB / 128, TT), 256, SM2>>>(
        hp, (size_t)BB * HH, HH, w2h, w2l, b2, hp, (size_t)BB * HH, HH);
    finalize_kernel<<<(TT * HH + 255) / 256, 256>>>(bn2_g, bn2_b, TT * HH, invB,
                                                    MBLK);

    // gemm3: out = relu(bn2(h)) @ W3 + b3
    g3<<<dim3(1, BB / 128, TT), 256, SM3>>>(
        hp, (size_t)BB * HH, HH, w3h, w3l, b3, out, (size_t)PP, TT * PP);
}

// round 7
// speedup vs baseline: 2.9687x; 1.2503x over previous
#include <cuda_runtime.h>
#include <cuda_fp16.h>
#include <cstdint>

// ============================================================================
// RNN_BN_simple, round 7: 2-product fp16 HMMA GEMMs, 2 CTAs/SM.
//  - x split into fp16 hi+lo (repr. error 2^-23); W a single rn fp16
//    (error 2^-12, dominant).  x*w ~= xh*w + xl*w : 2 MMA products (was 3).
//  - W SMEM halves -> BN=128 tiles fit 2 stages in 106KB -> 2 CTAs/SM,
//    hiding barrier and pipeline bubbles.
//  - BN affine (+ReLU) + split fused in the GEMM A-prologue, overlapped
//    under the first k16 sub-chunk; BN stats in the GEMM epilogue.
// ============================================================================

namespace {
constexpr int BB = 4096, TT = 64, PP = 64, HH = 512;
constexpr float BN_EPS = 1e-3f;
constexpr int SPLITS0 = 32;
constexpr int MBLK = BB / 128;
}

// ---------------- scratch ----------------------------------------------------
__device__ float g_h[(size_t)TT * BB * HH];
__device__ float g_psum[MBLK * TT * HH];
__device__ float g_psq [MBLK * TT * HH];
__device__ float g_s[TT * HH];
__device__ float g_c[TT * HH];
__device__ __align__(16) __half g_w1[(size_t)TT * PP * HH];
__device__ __align__(16) __half g_w2[(size_t)TT * HH * HH];
__device__ __align__(16) __half g_w3[(size_t)TT * HH * PP];

// ---------------- helpers ------------------------------------------------------
__device__ __forceinline__ uint32_t smem_u32(const void* p) {
    uint32_t a;
    asm("{ .reg .u64 t; cvta.to.shared.u64 t, %1; cvt.u32.u64 %0, t; }"
        : "=r"(a) : "l"(p));
    return a;
}
__device__ __forceinline__ void ldm_x4(uint32_t* r, uint32_t addr) {
    asm volatile("ldmatrix.sync.aligned.m8n8.x4.shared.b16 {%0,%1,%2,%3}, [%4];"
                 : "=r"(r[0]), "=r"(r[1]), "=r"(r[2]), "=r"(r[3]) : "r"(addr));
}
__device__ __forceinline__ void ldm_x4t(uint32_t* r, uint32_t addr) {
    asm volatile("ldmatrix.sync.aligned.m8n8.x4.trans.shared.b16 {%0,%1,%2,%3}, [%4];"
                 : "=r"(r[0]), "=r"(r[1]), "=r"(r[2]), "=r"(r[3]) : "r"(addr));
}
__device__ __forceinline__ void mma_f16(float* c, const uint32_t* a,
                                        const uint32_t* b) {
    asm volatile(
        "mma.sync.aligned.m16n8k16.row.col.f32.f16.f16.f32 "
        "{%0,%1,%2,%3}, {%4,%5,%6,%7}, {%8,%9}, {%0,%1,%2,%3};"
        : "+f"(c[0]), "+f"(c[1]), "+f"(c[2]), "+f"(c[3])
        : "r"(a[0]), "r"(a[1]), "r"(a[2]), "r"(a[3]), "r"(b[0]), "r"(b[1]));
}
__device__ __forceinline__ void cp16(uint32_t dst, const void* src) {
    asm volatile("cp.async.cg.shared.global [%0], [%1], 16;"
                 :: "r"(dst), "l"(src));
}
// fp16 split: hp = rn fp16 pair of (y0,y1),(y2,y3); lp = rn fp16 of remainder
__device__ __forceinline__ void split4h(float y0, float y1, float y2, float y3,
                                        uint2& hp, uint2& lp) {
    __half2 h01 = __floats2half2_rn(y0, y1);
    __half2 h23 = __floats2half2_rn(y2, y3);
    float2 f01 = __half22float2(h01);
    float2 f23 = __half22float2(h23);
    __half2 l01 = __floats2half2_rn(y0 - f01.x, y1 - f01.y);
    __half2 l23 = __floats2half2_rn(y2 - f23.x, y3 - f23.y);
    hp.x = *reinterpret_cast<uint32_t*>(&h01);
    hp.y = *reinterpret_cast<uint32_t*>(&h23);
    lp.x = *reinterpret_cast<uint32_t*>(&l01);
    lp.y = *reinterpret_cast<uint32_t*>(&l23);
}

// ---------------- BN stats for prices ------------------------------------------
__global__ void stats_kernel(const float* __restrict__ x, size_t t_stride,
                             int row_stride, int D, int rows_per_split) {
    const int t = blockIdx.x, split = blockIdx.y;
    const float* xt = x + (size_t)t * t_stride +
                      (size_t)split * rows_per_split * row_stride;
    for (int d = threadIdx.x; d < D; d += blockDim.x) {
        float s0 = 0.f, s1 = 0.f, q0 = 0.f, q1 = 0.f;
        #pragma unroll 2
        for (int r = 0; r < rows_per_split; r += 2) {
            float v0 = xt[(size_t)r * row_stride + d];
            float v1 = xt[(size_t)(r + 1) * row_stride + d];
            s0 += v0; q0 = fmaf(v0, v0, q0);
            s1 += v1; q1 = fmaf(v1, v1, q1);
        }
        int n = gridDim.x * D, i = t * D + d;
        g_psum[split * n + i] = s0 + s1;
        g_psq [split * n + i] = q0 + q1;
    }
}
__global__ void finalize_kernel(const float* __restrict__ gamma,
                                const float* __restrict__ beta, int n,
                                float invB, int nparts) {
    int i = blockIdx.x * blockDim.x + threadIdx.x;
    if (i >= n) return;
    float s = 0.f, q = 0.f;
    for (int sp = 0; sp < nparts; sp++) {
        s += g_psum[(size_t)sp * n + i];
        q += g_psq [(size_t)sp * n + i];
    }
    float m = s * invB;
    float v = fmaxf(fmaf(-m, m, q * invB), 0.f);
    float sc = gamma[i] * rsqrtf(v + BN_EPS);
    g_s[i] = sc;
    g_c[i] = fmaf(-m, sc, beta[i]);
}

// ---------------- weight prep: fp32 -> single rn fp16 ----------------------------
__global__ void prep_w(const float* __restrict__ W, __half* __restrict__ wh,
                       size_t nq) {
    size_t i = (size_t)blockIdx.x * blockDim.x + threadIdx.x;
    if (i >= nq) return;
    float4 w = ((const float4*)W)[i];
    __half2 a = __floats2half2_rn(w.x, w.y);
    __half2 b = __floats2half2_rn(w.z, w.w);
    ((uint2*)wh)[i] = make_uint2(*reinterpret_cast<uint32_t*>(&a),
                                 *reinterpret_cast<uint32_t*>(&b));
}

// ---------------- 2-product fp16 HMMA GEMM ---------------------------------------
// out[t,m,n] = sum_k prelu(A[t,m,k]*s+c) * W[t,k,n] + bias[t,n]
template <int BN, int BK, int KTOT, int NTOT, bool RELU, bool STATS>
__global__ void __launch_bounds__(256, 2)
gemm_mma(const float* __restrict__ A, size_t a_t, int a_rs,
         const __half* __restrict__ W,
         const float* __restrict__ bias,
         float* __restrict__ out, size_t o_t, int o_rs) {
    constexpr int BM = 128;
    constexpr int AROW = BK + 8, WROW = BN + 8;
    constexpr int A_BYTES = BM * AROW * 2, W_BYTES = BK * WROW * 2;
    constexpr int WHO = 2 * A_BYTES;                 // W after A hi+lo
    constexpr int STAGE = 2 * A_BYTES + W_BYTES;
    constexpr int KT = KTOT / BK;
    constexpr int WARPS_M = 2, WARPS_N = 4;
    constexpr int WTM = BM / WARPS_M, WTN = BN / WARPS_N;
    constexpr int MT = WTM / 16, NT = WTN / 8;
    constexpr int SEGS = BN / 8;
    constexpr int AV = BM * BK / (4 * 256);
    constexpr int KQL = BK / 4;
    constexpr int RPV = 256 / KQL;
    constexpr int NK16 = BK / 16;

    extern __shared__ char smem[];
    const uint32_t sb = smem_u32(smem);
    const int tid = threadIdx.x, wid = tid >> 5, lane = tid & 31;
    const int wm = wid / WARPS_N, wn = wid % WARPS_N;
    const int t = blockIdx.z, n0 = blockIdx.x * BN, m0 = blockIdx.y * BM;

    const int kq = tid % KQL, rowb = tid / KQL;
    const float* At = A + (size_t)t * a_t + (size_t)m0 * a_rs;
    const float* sArr = g_s + t * KTOT;
    const float* cArr = g_c + t * KTOT;
    const __half* WT = W + (size_t)t * KTOT * NTOT + n0;

    float4 areg[AV];
    float4 sv, cv;
    auto ldgA = [&](int kt) {
        const float* base = At + kt * BK + kq * 4;
        #pragma unroll
        for (int v = 0; v < AV; v++)
            areg[v] = *(const float4*)(base + (size_t)(rowb + v * RPV) * a_rs);
        sv = *(const float4*)(sArr + kt * BK + kq * 4);
        cv = *(const float4*)(cArr + kt * BK + kq * 4);
    };
    auto stsA = [&](int st) {
        char* hb = smem + st * STAGE;
        #pragma unroll
        for (int v = 0; v < AV; v++) {
            float y0 = fmaf(areg[v].x, sv.x, cv.x);
            float y1 = fmaf(areg[v].y, sv.y, cv.y);
            float y2 = fmaf(areg[v].z, sv.z, cv.z);
            float y3 = fmaf(areg[v].w, sv.w, cv.w);
            if (RELU) {
                y0 = fmaxf(y0, 0.f); y1 = fmaxf(y1, 0.f);
                y2 = fmaxf(y2, 0.f); y3 = fmaxf(y3, 0.f);
            }
            uint2 hp, lp;
            split4h(y0, y1, y2, y3, hp, lp);
            uint32_t off = (uint32_t)((rowb + v * RPV) * AROW + kq * 4) * 2;
            *(uint2*)(hb + off) = hp;
            *(uint2*)(hb + A_BYTES + off) = lp;
        }
    };
    auto cpW = [&](int kt, int st) {
        const uint32_t stb = sb + st * STAGE;
        #pragma unroll
        for (int i = tid; i < BK * SEGS; i += 256) {
            int row = i / SEGS, seg = i % SEGS;
            size_t g = (size_t)(kt * BK + row) * NTOT + seg * 8;
            cp16(stb + WHO + row * (WROW * 2) + seg * 16, WT + g);
        }
        asm volatile("cp.async.commit_group;" ::: "memory");
    };

    float acc[MT][NT][4];
    #pragma unroll
    for (int i = 0; i < MT; i++)
        #pragma unroll
        for (int j = 0; j < NT; j++)
            #pragma unroll
            for (int k = 0; k < 4; k++) acc[i][j][k] = 0.f;

    const int lrow = lane & 15, lsel = lane >> 4;

    auto compute_k16 = [&](uint32_t stb, int k16) {
        uint32_t ah[MT][4], al[MT][4];
        #pragma unroll
        for (int mt = 0; mt < MT; mt++) {
            uint32_t off = (uint32_t)((wm * WTM + mt * 16 + lrow) * AROW +
                                      k16 * 16 + lsel * 8) * 2;
            ldm_x4(ah[mt], stb + off);
            ldm_x4(al[mt], stb + A_BYTES + off);
        }
        uint32_t bq[NT][2];
        #pragma unroll
        for (int np = 0; np < NT / 2; np++) {
            uint32_t off = (uint32_t)((k16 * 16 + lrow) * WROW + wn * WTN +
                                      np * 16 + lsel * 8) * 2;
            uint32_t r[4];
            ldm_x4t(r, stb + WHO + off);
            bq[2*np][0] = r[0]; bq[2*np][1] = r[1];
            bq[2*np+1][0] = r[2]; bq[2*np+1][1] = r[3];
        }
        #pragma unroll
        for (int mt = 0; mt < MT; mt++)
            #pragma unroll
            for (int nt = 0; nt < NT; nt++) mma_f16(acc[mt][nt], ah[mt], bq[nt]);
        #pragma unroll
        for (int mt = 0; mt < MT; mt++)
            #pragma unroll
            for (int nt = 0; nt < NT; nt++) mma_f16(acc[mt][nt], al[mt], bq[nt]);
    };

    // prologue
    ldgA(0);
    cpW(0, 0);
    stsA(0);

    #pragma unroll 1
    for (int kt = 0; kt < KT; kt++) {
        const int st = kt & 1;
        asm volatile("cp.async.wait_group 0;" ::: "memory");
        __syncthreads();
        const bool more = (kt + 1 < KT);
        if (more) { cpW(kt + 1, st ^ 1); ldgA(kt + 1); }
        const uint32_t stb = sb + st * STAGE;
        compute_k16(stb, 0);
        if (more) stsA(st ^ 1);      // overlapped: writes the other stage
        #pragma unroll
        for (int k16 = 1; k16 < NK16; k16++) compute_k16(stb, k16);
    }
    __syncthreads();   // smem reused below for stats

    // ---- epilogue: bias, store, optional column stats ----
    const int r0 = lane >> 2, c0 = (lane & 3) * 2;
    #pragma unroll
    for (int nt = 0; nt < NT; nt++) {
        float2 bv = *(const float2*)(bias + t * NTOT + n0 + wn * WTN + nt * 8 + c0);
        #pragma unroll
        for (int mt = 0; mt < MT; mt++) {
            acc[mt][nt][0] += bv.x; acc[mt][nt][1] += bv.y;
            acc[mt][nt][2] += bv.x; acc[mt][nt][3] += bv.y;
        }
    }
    #pragma unroll
    for (int mt = 0; mt < MT; mt++) {
        #pragma unroll
        for (int nt = 0; nt < NT; nt++) {
            int col = n0 + wn * WTN + nt * 8 + c0;
            int row = m0 + wm * WTM + mt * 16 + r0;
            float* p0 = out + (size_t)t * o_t + (size_t)row * o_rs + col;
            float* p1 = p0 + (size_t)8 * o_rs;
            *(float2*)p0 = make_float2(acc[mt][nt][0], acc[mt][nt][1]);
            *(float2*)p1 = make_float2(acc[mt][nt][2], acc[mt][nt][3]);
        }
    }
    if (STATS) {
        float* sbuf = (float*)smem;   // [2 wm][2 kind][BN]
        #pragma unroll
        for (int nt = 0; nt < NT; nt++) {
            #pragma unroll
            for (int j = 0; j < 2; j++) {
                float s = 0.f, q = 0.f;
                #pragma unroll
                for (int mt = 0; mt < MT; mt++) {
                    float v0 = acc[mt][nt][j], v1 = acc[mt][nt][2 + j];
                    s += v0 + v1;
                    q = fmaf(v0, v0, q); q = fmaf(v1, v1, q);
                }
                #pragma unroll
                for (int msk = 4; msk <= 16; msk <<= 1) {
                    s += __shfl_xor_sync(0xffffffffu, s, msk);
                    q += __shfl_xor_sync(0xffffffffu, q, msk);
                }
                if (r0 == 0) {
                    int col = wn * WTN + nt * 8 + c0 + j;
                    sbuf[(wm * 2 + 0) * BN + col] = s;
                    sbuf[(wm * 2 + 1) * BN + col] = q;
                }
            }
        }
        __syncthreads();
        for (int cix = tid; cix < BN; cix += 256) {
            float ss = sbuf[0 * BN + cix] + sbuf[2 * BN + cix];
            float qq = sbuf[1 * BN + cix] + sbuf[3 * BN + cix];
            size_t pi = (size_t)blockIdx.y * (TT * NTOT) + (size_t)t * NTOT + n0 + cix;
            g_psum[pi] = ss;
            g_psq [pi] = qq;
        }
    }
}

// ---------------- launch --------------------------------------------------------
extern "C" void kernel_launch(void* const* d_in, const int* in_sizes, int n_in,
                              void* d_out, int out_size) {
    (void)in_sizes; (void)n_in; (void)out_size;
    const float* prices = (const float*)d_in[0];
    const float* bn0_g  = (const float*)d_in[1];
    const float* bn0_b  = (const float*)d_in[2];
    const float* W1     = (const float*)d_in[3];
    const float* b1     = (const float*)d_in[4];
    const float* bn1_g  = (const float*)d_in[5];
    const float* bn1_b  = (const float*)d_in[6];
    const float* W2     = (const float*)d_in[7];
    const float* b2     = (const float*)d_in[8];
    const float* bn2_g  = (const float*)d_in[9];
    const float* bn2_b  = (const float*)d_in[10];
    const float* W3     = (const float*)d_in[11];
    const float* b3     = (const float*)d_in[12];
    float* out = (float*)d_out;

    float* hp;
    __half *w1, *w2, *w3;
    cudaGetSymbolAddress((void**)&hp, g_h);
    cudaGetSymbolAddress((void**)&w1, g_w1);
    cudaGetSymbolAddress((void**)&w2, g_w2);
    cudaGetSymbolAddress((void**)&w3, g_w3);

    const float invB = 1.0f / (float)BB;

    auto g1 = gemm_mma<128, 64, 64,  512, false, true>;
    auto g2 = gemm_mma<128, 64, 512, 512, true,  true>;
    auto g3 = gemm_mma<64,  64, 512, 64,  true,  false>;
    // STAGE: 2*(128*72*2) + 64*(BN+8)*2
    constexpr int STAGE_128 = 2 * (128 * 72 * 2) + 64 * 136 * 2;  // 54272
    constexpr int STAGE_64  = 2 * (128 * 72 * 2) + 64 * 72 * 2;   // 46080
    constexpr int SM1 = 1 * STAGE_128;
    constexpr int SM2 = 2 * STAGE_128;    // 108544
    constexpr int SM3 = 2 * STAGE_64;     // 92160
    cudaFuncSetAttribute(g1, cudaFuncAttributeMaxDynamicSharedMemorySize, SM1);
    cudaFuncSetAttribute(g2, cudaFuncAttributeMaxDynamicSharedMemorySize, SM2);
    cudaFuncSetAttribute(g3, cudaFuncAttributeMaxDynamicSharedMemorySize, SM3);

    // weight prep (single fp16)
    prep_w<<<(int)(((size_t)TT*PP*HH/4 + 255)/256), 256>>>(W1, w1, (size_t)TT*PP*HH/4);
    prep_w<<<(int)(((size_t)TT*HH*HH/4 + 255)/256), 256>>>(W2, w2, (size_t)TT*HH*HH/4);
    prep_w<<<(int)(((size_t)TT*HH*PP/4 + 255)/256), 256>>>(W3, w3, (size_t)TT*HH*PP/4);

    // BN0 stats on prices
    stats_kernel<<<dim3(TT, SPLITS0), 64>>>(prices, (size_t)PP, TT * PP, PP,
                                            BB / SPLITS0);
    finalize_kernel<<<(TT * PP + 255) / 256, 256>>>(bn0_g, bn0_b, TT * PP, invB,
                                                    SPLITS0);

    // gemm1: h = bn0(prices) @ W1 + b1, stats partials for BN1
    g1<<<dim3(HH / 128, BB / 128, TT), 256, SM1>>>(
        prices, (size_t)PP, TT * PP, w1, b1, hp, (size_t)BB * HH, HH);
    finalize_kernel<<<(TT * HH + 255) / 256, 256>>>(bn1_g, bn1_b, TT * HH, invB,
                                                    MBLK);

    // gemm2: h = relu(bn1(h)) @ W2 + b2, stats partials for BN2
    g2<<<dim3(HH / 128, BB / 128, TT), 256, SM2>>>(
        hp, (size_t)BB * HH, HH, w2, b2, hp, (size_t)BB * HH, HH);
    finalize_kernel<<<(TT * HH + 255) / 256, 256>>>(bn2_g, bn2_b, TT * HH, invB,
                                                    MBLK);

    // gemm3: out = relu(bn2(h)) @ W3 + b3
    g3<<<dim3(1, BB / 128, TT), 256, SM3>>>(
        hp, (size_t)BB * HH, HH, w3, b3, out, (size_t)PP, TT * PP);
}

// round 8
// speedup vs baseline: 3.2695x; 1.1014x over previous
#include <cuda_runtime.h>
#include <cuda_fp16.h>
#include <cstdint>

// ============================================================================
// RNN_BN_simple, round 8: 2-product fp16 HMMA on the wide (BN=256) tile.
//  - x split into fp16 hi+lo (repr. error 2^-23); W single rn fp16 (2^-12).
//    x*w ~= xh*w + xl*w : 2 MMA products.
//  - BN=256/BK=64 tile (round-6 shape): LDSM/HMMA ratio 0.19, A-convert
//    duplicated only 2x for GEMM2. 1 CTA/SM, 256 threads, acc=128 regs.
//  - BN affine (+ReLU) + split fused in GEMM A-prologue, overlapped under
//    the first k16 sub-chunk; BN stats in the GEMM epilogue.
// ============================================================================

namespace {
constexpr int BB = 4096, TT = 64, PP = 64, HH = 512;
constexpr float BN_EPS = 1e-3f;
constexpr int SPLITS0 = 32;
constexpr int MBLK = BB / 128;
}

// ---------------- scratch ----------------------------------------------------
__device__ float g_h[(size_t)TT * BB * HH];
__device__ float g_psum[MBLK * TT * HH];
__device__ float g_psq [MBLK * TT * HH];
__device__ float g_s[TT * HH];
__device__ float g_c[TT * HH];
__device__ __align__(16) __half g_w1[(size_t)TT * PP * HH];
__device__ __align__(16) __half g_w2[(size_t)TT * HH * HH];
__device__ __align__(16) __half g_w3[(size_t)TT * HH * PP];

// ---------------- helpers ------------------------------------------------------
__device__ __forceinline__ uint32_t smem_u32(const void* p) {
    uint32_t a;
    asm("{ .reg .u64 t; cvta.to.shared.u64 t, %1; cvt.u32.u64 %0, t; }"
        : "=r"(a) : "l"(p));
    return a;
}
__device__ __forceinline__ void ldm_x4(uint32_t* r, uint32_t addr) {
    asm volatile("ldmatrix.sync.aligned.m8n8.x4.shared.b16 {%0,%1,%2,%3}, [%4];"
                 : "=r"(r[0]), "=r"(r[1]), "=r"(r[2]), "=r"(r[3]) : "r"(addr));
}
__device__ __forceinline__ void ldm_x4t(uint32_t* r, uint32_t addr) {
    asm volatile("ldmatrix.sync.aligned.m8n8.x4.trans.shared.b16 {%0,%1,%2,%3}, [%4];"
                 : "=r"(r[0]), "=r"(r[1]), "=r"(r[2]), "=r"(r[3]) : "r"(addr));
}
__device__ __forceinline__ void mma_f16(float* c, const uint32_t* a,
                                        const uint32_t* b) {
    asm volatile(
        "mma.sync.aligned.m16n8k16.row.col.f32.f16.f16.f32 "
        "{%0,%1,%2,%3}, {%4,%5,%6,%7}, {%8,%9}, {%0,%1,%2,%3};"
        : "+f"(c[0]), "+f"(c[1]), "+f"(c[2]), "+f"(c[3])
        : "r"(a[0]), "r"(a[1]), "r"(a[2]), "r"(a[3]), "r"(b[0]), "r"(b[1]));
}
__device__ __forceinline__ void cp16(uint32_t dst, const void* src) {
    asm volatile("cp.async.cg.shared.global [%0], [%1], 16;"
                 :: "r"(dst), "l"(src));
}
// fp16 split: hp = rn fp16 pair of (y0,y1),(y2,y3); lp = rn fp16 of remainder
__device__ __forceinline__ void split4h(float y0, float y1, float y2, float y3,
                                        uint2& hp, uint2& lp) {
    __half2 h01 = __floats2half2_rn(y0, y1);
    __half2 h23 = __floats2half2_rn(y2, y3);
    float2 f01 = __half22float2(h01);
    float2 f23 = __half22float2(h23);
    __half2 l01 = __floats2half2_rn(y0 - f01.x, y1 - f01.y);
    __half2 l23 = __floats2half2_rn(y2 - f23.x, y3 - f23.y);
    hp.x = *reinterpret_cast<uint32_t*>(&h01);
    hp.y = *reinterpret_cast<uint32_t*>(&h23);
    lp.x = *reinterpret_cast<uint32_t*>(&l01);
    lp.y = *reinterpret_cast<uint32_t*>(&l23);
}

// ---------------- BN stats for prices ------------------------------------------
__global__ void stats_kernel(const float* __restrict__ x, size_t t_stride,
                             int row_stride, int D, int rows_per_split) {
    const int t = blockIdx.x, split = blockIdx.y;
    const float* xt = x + (size_t)t * t_stride +
                      (size_t)split * rows_per_split * row_stride;
    for (int d = threadIdx.x; d < D; d += blockDim.x) {
        float s0 = 0.f, s1 = 0.f, q0 = 0.f, q1 = 0.f;
        #pragma unroll 2
        for (int r = 0; r < rows_per_split; r += 2) {
            float v0 = xt[(size_t)r * row_stride + d];
            float v1 = xt[(size_t)(r + 1) * row_stride + d];
            s0 += v0; q0 = fmaf(v0, v0, q0);
            s1 += v1; q1 = fmaf(v1, v1, q1);
        }
        int n = gridDim.x * D, i = t * D + d;
        g_psum[split * n + i] = s0 + s1;
        g_psq [split * n + i] = q0 + q1;
    }
}
__global__ void finalize_kernel(const float* __restrict__ gamma,
                                const float* __restrict__ beta, int n,
                                float invB, int nparts) {
    int i = blockIdx.x * blockDim.x + threadIdx.x;
    if (i >= n) return;
    float s = 0.f, q = 0.f;
    for (int sp = 0; sp < nparts; sp++) {
        s += g_psum[(size_t)sp * n + i];
        q += g_psq [(size_t)sp * n + i];
    }
    float m = s * invB;
    float v = fmaxf(fmaf(-m, m, q * invB), 0.f);
    float sc = gamma[i] * rsqrtf(v + BN_EPS);
    g_s[i] = sc;
    g_c[i] = fmaf(-m, sc, beta[i]);
}

// ---------------- weight prep: fp32 -> single rn fp16 ----------------------------
__global__ void prep_w(const float* __restrict__ W, __half* __restrict__ wh,
                       size_t nq) {
    size_t i = (size_t)blockIdx.x * blockDim.x + threadIdx.x;
    if (i >= nq) return;
    float4 w = ((const float4*)W)[i];
    __half2 a = __floats2half2_rn(w.x, w.y);
    __half2 b = __floats2half2_rn(w.z, w.w);
    ((uint2*)wh)[i] = make_uint2(*reinterpret_cast<uint32_t*>(&a),
                                 *reinterpret_cast<uint32_t*>(&b));
}

// ---------------- 2-product fp16 HMMA GEMM ---------------------------------------
// out[t,m,n] = sum_k prelu(A[t,m,k]*s+c) * W[t,k,n] + bias[t,n]
template <int BN, int BK, int KTOT, int NTOT, bool RELU, bool STATS>
__global__ void __launch_bounds__(256)
gemm_mma(const float* __restrict__ A, size_t a_t, int a_rs,
         const __half* __restrict__ W,
         const float* __restrict__ bias,
         float* __restrict__ out, size_t o_t, int o_rs) {
    constexpr int BM = 128;
    constexpr int AROW = BK + 8, WROW = BN + 8;
    constexpr int A_BYTES = BM * AROW * 2, W_BYTES = BK * WROW * 2;
    constexpr int WHO = 2 * A_BYTES;                 // W after A hi+lo
    constexpr int STAGE = 2 * A_BYTES + W_BYTES;
    constexpr int KT = KTOT / BK;
    constexpr int WARPS_M = 2, WARPS_N = 4;
    constexpr int WTM = BM / WARPS_M, WTN = BN / WARPS_N;
    constexpr int MT = WTM / 16, NT = WTN / 8;
    constexpr int SEGS = BN / 8;
    constexpr int AV = BM * BK / (4 * 256);
    constexpr int KQL = BK / 4;
    constexpr int RPV = 256 / KQL;
    constexpr int NK16 = BK / 16;

    extern __shared__ char smem[];
    const uint32_t sb = smem_u32(smem);
    const int tid = threadIdx.x, wid = tid >> 5, lane = tid & 31;
    const int wm = wid / WARPS_N, wn = wid % WARPS_N;
    const int t = blockIdx.z, n0 = blockIdx.x * BN, m0 = blockIdx.y * BM;

    const int kq = tid % KQL, rowb = tid / KQL;
    const float* At = A + (size_t)t * a_t + (size_t)m0 * a_rs;
    const float* sArr = g_s + t * KTOT;
    const float* cArr = g_c + t * KTOT;
    const __half* WT = W + (size_t)t * KTOT * NTOT + n0;

    float4 areg[AV];
    float4 sv, cv;
    auto ldgA = [&](int kt) {
        const float* base = At + kt * BK + kq * 4;
        #pragma unroll
        for (int v = 0; v < AV; v++)
            areg[v] = *(const float4*)(base + (size_t)(rowb + v * RPV) * a_rs);
        sv = *(const float4*)(sArr + kt * BK + kq * 4);
        cv = *(const float4*)(cArr + kt * BK + kq * 4);
    };
    auto stsA = [&](int st) {
        char* hb = smem + st * STAGE;
        #pragma unroll
        for (int v = 0; v < AV; v++) {
            float y0 = fmaf(areg[v].x, sv.x, cv.x);
            float y1 = fmaf(areg[v].y, sv.y, cv.y);
            float y2 = fmaf(areg[v].z, sv.z, cv.z);
            float y3 = fmaf(areg[v].w, sv.w, cv.w);
            if (RELU) {
                y0 = fmaxf(y0, 0.f); y1 = fmaxf(y1, 0.f);
                y2 = fmaxf(y2, 0.f); y3 = fmaxf(y3, 0.f);
            }
            uint2 hp, lp;
            split4h(y0, y1, y2, y3, hp, lp);
            uint32_t off = (uint32_t)((rowb + v * RPV) * AROW + kq * 4) * 2;
            *(uint2*)(hb + off) = hp;
            *(uint2*)(hb + A_BYTES + off) = lp;
        }
    };
    auto cpW = [&](int kt, int st) {
        const uint32_t stb = sb + st * STAGE;
        #pragma unroll
        for (int i = tid; i < BK * SEGS; i += 256) {
            int row = i / SEGS, seg = i % SEGS;
            size_t g = (size_t)(kt * BK + row) * NTOT + seg * 8;
            cp16(stb + WHO + row * (WROW * 2) + seg * 16, WT + g);
        }
        asm volatile("cp.async.commit_group;" ::: "memory");
    };

    float acc[MT][NT][4];
    #pragma unroll
    for (int i = 0; i < MT; i++)
        #pragma unroll
        for (int j = 0; j < NT; j++)
            #pragma unroll
            for (int k = 0; k < 4; k++) acc[i][j][k] = 0.f;

    const int lrow = lane & 15, lsel = lane >> 4;

    auto compute_k16 = [&](uint32_t stb, int k16) {
        uint32_t ah[MT][4], al[MT][4];
        #pragma unroll
        for (int mt = 0; mt < MT; mt++) {
            uint32_t off = (uint32_t)((wm * WTM + mt * 16 + lrow) * AROW +
                                      k16 * 16 + lsel * 8) * 2;
            ldm_x4(ah[mt], stb + off);
            ldm_x4(al[mt], stb + A_BYTES + off);
        }
        uint32_t bq[NT][2];
        #pragma unroll
        for (int np = 0; np < NT / 2; np++) {
            uint32_t off = (uint32_t)((k16 * 16 + lrow) * WROW + wn * WTN +
                                      np * 16 + lsel * 8) * 2;
            uint32_t r[4];
            ldm_x4t(r, stb + WHO + off);
            bq[2*np][0] = r[0]; bq[2*np][1] = r[1];
            bq[2*np+1][0] = r[2]; bq[2*np+1][1] = r[3];
        }
        #pragma unroll
        for (int mt = 0; mt < MT; mt++)
            #pragma unroll
            for (int nt = 0; nt < NT; nt++) mma_f16(acc[mt][nt], ah[mt], bq[nt]);
        #pragma unroll
        for (int mt = 0; mt < MT; mt++)
            #pragma unroll
            for (int nt = 0; nt < NT; nt++) mma_f16(acc[mt][nt], al[mt], bq[nt]);
    };

    // prologue
    ldgA(0);
    cpW(0, 0);
    stsA(0);

    #pragma unroll 1
    for (int kt = 0; kt < KT; kt++) {
        const int st = kt & 1;
        asm volatile("cp.async.wait_group 0;" ::: "memory");
        __syncthreads();
        const bool more = (kt + 1 < KT);
        if (more) { cpW(kt + 1, st ^ 1); ldgA(kt + 1); }
        const uint32_t stb = sb + st * STAGE;
        compute_k16(stb, 0);
        if (more) stsA(st ^ 1);      // overlapped: writes the other stage
        #pragma unroll
        for (int k16 = 1; k16 < NK16; k16++) compute_k16(stb, k16);
    }
    __syncthreads();   // smem reused below for stats

    // ---- epilogue: bias, store, optional column stats ----
    const int r0 = lane >> 2, c0 = (lane & 3) * 2;
    #pragma unroll
    for (int nt = 0; nt < NT; nt++) {
        float2 bv = *(const float2*)(bias + t * NTOT + n0 + wn * WTN + nt * 8 + c0);
        #pragma unroll
        for (int mt = 0; mt < MT; mt++) {
            acc[mt][nt][0] += bv.x; acc[mt][nt][1] += bv.y;
            acc[mt][nt][2] += bv.x; acc[mt][nt][3] += bv.y;
        }
    }
    #pragma unroll
    for (int mt = 0; mt < MT; mt++) {
        #pragma unroll
        for (int nt = 0; nt < NT; nt++) {
            int col = n0 + wn * WTN + nt * 8 + c0;
            int row = m0 + wm * WTM + mt * 16 + r0;
            float* p0 = out + (size_t)t * o_t + (size_t)row * o_rs + col;
            float* p1 = p0 + (size_t)8 * o_rs;
            *(float2*)p0 = make_float2(acc[mt][nt][0], acc[mt][nt][1]);
            *(float2*)p1 = make_float2(acc[mt][nt][2], acc[mt][nt][3]);
        }
    }
    if (STATS) {
        float* sbuf = (float*)smem;   // [2 wm][2 kind][BN]
        #pragma unroll
        for (int nt = 0; nt < NT; nt++) {
            #pragma unroll
            for (int j = 0; j < 2; j++) {
                float s = 0.f, q = 0.f;
                #pragma unroll
                for (int mt = 0; mt < MT; mt++) {
                    float v0 = acc[mt][nt][j], v1 = acc[mt][nt][2 + j];
                    s += v0 + v1;
                    q = fmaf(v0, v0, q); q = fmaf(v1, v1, q);
                }
                #pragma unroll
                for (int msk = 4; msk <= 16; msk <<= 1) {
                    s += __shfl_xor_sync(0xffffffffu, s, msk);
                    q += __shfl_xor_sync(0xffffffffu, q, msk);
                }
                if (r0 == 0) {
                    int col = wn * WTN + nt * 8 + c0 + j;
                    sbuf[(wm * 2 + 0) * BN + col] = s;
                    sbuf[(wm * 2 + 1) * BN + col] = q;
                }
            }
        }
        __syncthreads();
        for (int cix = tid; cix < BN; cix += 256) {
            float ss = sbuf[0 * BN + cix] + sbuf[2 * BN + cix];
            float qq = sbuf[1 * BN + cix] + sbuf[3 * BN + cix];
            size_t pi = (size_t)blockIdx.y * (TT * NTOT) + (size_t)t * NTOT + n0 + cix;
            g_psum[pi] = ss;
            g_psq [pi] = qq;
        }
    }
}

// ---------------- launch --------------------------------------------------------
extern "C" void kernel_launch(void* const* d_in, const int* in_sizes, int n_in,
                              void* d_out, int out_size) {
    (void)in_sizes; (void)n_in; (void)out_size;
    const float* prices = (const float*)d_in[0];
    const float* bn0_g  = (const float*)d_in[1];
    const float* bn0_b  = (const float*)d_in[2];
    const float* W1     = (const float*)d_in[3];
    const float* b1     = (const float*)d_in[4];
    const float* bn1_g  = (const float*)d_in[5];
    const float* bn1_b  = (const float*)d_in[6];
    const float* W2     = (const float*)d_in[7];
    const float* b2     = (const float*)d_in[8];
    const float* bn2_g  = (const float*)d_in[9];
    const float* bn2_b  = (const float*)d_in[10];
    const float* W3     = (const float*)d_in[11];
    const float* b3     = (const float*)d_in[12];
    float* out = (float*)d_out;

    float* hp;
    __half *w1, *w2, *w3;
    cudaGetSymbolAddress((void**)&hp, g_h);
    cudaGetSymbolAddress((void**)&w1, g_w1);
    cudaGetSymbolAddress((void**)&w2, g_w2);
    cudaGetSymbolAddress((void**)&w3, g_w3);

    const float invB = 1.0f / (float)BB;

    auto g1 = gemm_mma<256, 64, 64,  512, false, true>;
    auto g2 = gemm_mma<256, 64, 512, 512, true,  true>;
    auto g3 = gemm_mma<64,  64, 512, 64,  true,  false>;
    // STAGE: 2*(128*72*2) + 64*(BN+8)*2
    constexpr int STAGE_256 = 2 * (128 * 72 * 2) + 64 * 264 * 2;  // 70656
    constexpr int STAGE_64  = 2 * (128 * 72 * 2) + 64 * 72 * 2;   // 46080
    constexpr int SM1 = 1 * STAGE_256;    // KT=1 -> single stage
    constexpr int SM2 = 2 * STAGE_256;    // 141312
    constexpr int SM3 = 2 * STAGE_64;     // 92160
    cudaFuncSetAttribute(g1, cudaFuncAttributeMaxDynamicSharedMemorySize, SM1);
    cudaFuncSetAttribute(g2, cudaFuncAttributeMaxDynamicSharedMemorySize, SM2);
    cudaFuncSetAttribute(g3, cudaFuncAttributeMaxDynamicSharedMemorySize, SM3);

    // weight prep (single fp16)
    prep_w<<<(int)(((size_t)TT*PP*HH/4 + 255)/256), 256>>>(W1, w1, (size_t)TT*PP*HH/4);
    prep_w<<<(int)(((size_t)TT*HH*HH/4 + 255)/256), 256>>>(W2, w2, (size_t)TT*HH*HH/4);
    prep_w<<<(int)(((size_t)TT*HH*PP/4 + 255)/256), 256>>>(W3, w3, (size_t)TT*HH*PP/4);

    // BN0 stats on prices
    stats_kernel<<<dim3(TT, SPLITS0), 64>>>(prices, (size_t)PP, TT * PP, PP,
                                            BB / SPLITS0);
    finalize_kernel<<<(TT * PP + 255) / 256, 256>>>(bn0_g, bn0_b, TT * PP, invB,
                                                    SPLITS0);

    // gemm1: h = bn0(prices) @ W1 + b1, stats partials for BN1
    g1<<<dim3(HH / 256, BB / 128, TT), 256, SM1>>>(
        prices, (size_t)PP, TT * PP, w1, b1, hp, (size_t)BB * HH, HH);
    finalize_kernel<<<(TT * HH + 255) / 256, 256>>>(bn1_g, bn1_b, TT * HH, invB,
                                                    MBLK);

    // gemm2: h = relu(bn1(h)) @ W2 + b2, stats partials for BN2
    g2<<<dim3(HH / 256, BB / 128, TT), 256, SM2>>>(
        hp, (size_t)BB * HH, HH, w2, b2, hp, (size_t)BB * HH, HH);
    finalize_kernel<<<(TT * HH + 255) / 256, 256>>>(bn2_g, bn2_b, TT * HH, invB,
                                                    MBLK);

    // gemm3: out = relu(bn2(h)) @ W3 + b3
    g3<<<dim3(1, BB / 128, TT), 256, SM3>>>(
        hp, (size_t)BB * HH, HH, w3, b3, out, (size_t)PP, TT * PP);
}

// round 9
// speedup vs baseline: 4.2167x; 1.2897x over previous
#include <cuda_runtime.h>
#include <cuda_fp16.h>
#include <cstdint>

// ============================================================================
// RNN_BN_simple, round 9: single-product fp16 HMMA (calibrated-error bet).
//  - x rn fp16 (err 2^-12) * W rn fp16 (err 2^-12): ONE MMA product.
//    Calibrated model: 2-product measured 3.84e-4 (W-quant only);
//    single-product adds equal independent x-quant -> ~5.4e-4 < 1e-3 gate.
//  - BN=256/BK=64 tile (round-8 shape), BN affine (+ReLU) + fp16 convert in
//    the GEMM A-prologue overlapped under the first k16; BN stats in epilogue.
//  - Launch order puts g1 at ncu capture index to finally profile a GEMM.
// ============================================================================

namespace {
constexpr int BB = 4096, TT = 64, PP = 64, HH = 512;
constexpr float BN_EPS = 1e-3f;
constexpr int SPLITS0 = 32;
constexpr int MBLK = BB / 128;
}

// ---------------- scratch ----------------------------------------------------
__device__ float g_h[(size_t)TT * BB * HH];
__device__ float g_psum[MBLK * TT * HH];
__device__ float g_psq [MBLK * TT * HH];
__device__ float g_s[TT * HH];
__device__ float g_c[TT * HH];
__device__ __align__(16) __half g_w1[(size_t)TT * PP * HH];
__device__ __align__(16) __half g_w2[(size_t)TT * HH * HH];
__device__ __align__(16) __half g_w3[(size_t)TT * HH * PP];

// ---------------- helpers ------------------------------------------------------
__device__ __forceinline__ uint32_t smem_u32(const void* p) {
    uint32_t a;
    asm("{ .reg .u64 t; cvta.to.shared.u64 t, %1; cvt.u32.u64 %0, t; }"
        : "=r"(a) : "l"(p));
    return a;
}
__device__ __forceinline__ void ldm_x4(uint32_t* r, uint32_t addr) {
    asm volatile("ldmatrix.sync.aligned.m8n8.x4.shared.b16 {%0,%1,%2,%3}, [%4];"
                 : "=r"(r[0]), "=r"(r[1]), "=r"(r[2]), "=r"(r[3]) : "r"(addr));
}
__device__ __forceinline__ void ldm_x4t(uint32_t* r, uint32_t addr) {
    asm volatile("ldmatrix.sync.aligned.m8n8.x4.trans.shared.b16 {%0,%1,%2,%3}, [%4];"
                 : "=r"(r[0]), "=r"(r[1]), "=r"(r[2]), "=r"(r[3]) : "r"(addr));
}
__device__ __forceinline__ void mma_f16(float* c, const uint32_t* a,
                                        const uint32_t* b) {
    asm volatile(
        "mma.sync.aligned.m16n8k16.row.col.f32.f16.f16.f32 "
        "{%0,%1,%2,%3}, {%4,%5,%6,%7}, {%8,%9}, {%0,%1,%2,%3};"
        : "+f"(c[0]), "+f"(c[1]), "+f"(c[2]), "+f"(c[3])
        : "r"(a[0]), "r"(a[1]), "r"(a[2]), "r"(a[3]), "r"(b[0]), "r"(b[1]));
}
__device__ __forceinline__ void cp16(uint32_t dst, const void* src) {
    asm volatile("cp.async.cg.shared.global [%0], [%1], 16;"
                 :: "r"(dst), "l"(src));
}
// pack 4 fp32 -> 4 rn fp16 in a uint2
__device__ __forceinline__ uint2 pack4h(float y0, float y1, float y2, float y3) {
    __half2 h01 = __floats2half2_rn(y0, y1);
    __half2 h23 = __floats2half2_rn(y2, y3);
    return make_uint2(*reinterpret_cast<uint32_t*>(&h01),
                      *reinterpret_cast<uint32_t*>(&h23));
}

// ---------------- BN stats for prices ------------------------------------------
__global__ void stats_kernel(const float* __restrict__ x, size_t t_stride,
                             int row_stride, int D, int rows_per_split) {
    const int t = blockIdx.x, split = blockIdx.y;
    const float* xt = x + (size_t)t * t_stride +
                      (size_t)split * rows_per_split * row_stride;
    for (int d = threadIdx.x; d < D; d += blockDim.x) {
        float s0 = 0.f, s1 = 0.f, q0 = 0.f, q1 = 0.f;
        #pragma unroll 2
        for (int r = 0; r < rows_per_split; r += 2) {
            float v0 = xt[(size_t)r * row_stride + d];
            float v1 = xt[(size_t)(r + 1) * row_stride + d];
            s0 += v0; q0 = fmaf(v0, v0, q0);
            s1 += v1; q1 = fmaf(v1, v1, q1);
        }
        int n = gridDim.x * D, i = t * D + d;
        g_psum[split * n + i] = s0 + s1;
        g_psq [split * n + i] = q0 + q1;
    }
}
__global__ void finalize_kernel(const float* __restrict__ gamma,
                                const float* __restrict__ beta, int n,
                                float invB, int nparts) {
    int i = blockIdx.x * blockDim.x + threadIdx.x;
    if (i >= n) return;
    float s = 0.f, q = 0.f;
    for (int sp = 0; sp < nparts; sp++) {
        s += g_psum[(size_t)sp * n + i];
        q += g_psq [(size_t)sp * n + i];
    }
    float m = s * invB;
    float v = fmaxf(fmaf(-m, m, q * invB), 0.f);
    float sc = gamma[i] * rsqrtf(v + BN_EPS);
    g_s[i] = sc;
    g_c[i] = fmaf(-m, sc, beta[i]);
}

// ---------------- weight prep: fp32 -> single rn fp16 ----------------------------
__global__ void prep_w(const float* __restrict__ W, __half* __restrict__ wh,
                       size_t nq) {
    size_t i = (size_t)blockIdx.x * blockDim.x + threadIdx.x;
    if (i >= nq) return;
    float4 w = ((const float4*)W)[i];
    ((uint2*)wh)[i] = pack4h(w.x, w.y, w.z, w.w);
}

// ---------------- single-product fp16 HMMA GEMM -----------------------------------
// out[t,m,n] = sum_k prelu(A[t,m,k]*s+c) * W[t,k,n] + bias[t,n]
template <int BN, int BK, int KTOT, int NTOT, bool RELU, bool STATS>
__global__ void __launch_bounds__(256)
gemm_mma(const float* __restrict__ A, size_t a_t, int a_rs,
         const __half* __restrict__ W,
         const float* __restrict__ bias,
         float* __restrict__ out, size_t o_t, int o_rs) {
    constexpr int BM = 128;
    constexpr int AROW = BK + 8, WROW = BN + 8;
    constexpr int A_BYTES = BM * AROW * 2, W_BYTES = BK * WROW * 2;
    constexpr int WHO = A_BYTES;                     // W right after A
    constexpr int STAGE = A_BYTES + W_BYTES;
    constexpr int KT = KTOT / BK;
    constexpr int WARPS_M = 2, WARPS_N = 4;
    constexpr int WTM = BM / WARPS_M, WTN = BN / WARPS_N;
    constexpr int MT = WTM / 16, NT = WTN / 8;
    constexpr int SEGS = BN / 8;
    constexpr int AV = BM * BK / (4 * 256);
    constexpr int KQL = BK / 4;
    constexpr int RPV = 256 / KQL;
    constexpr int NK16 = BK / 16;

    extern __shared__ char smem[];
    const uint32_t sb = smem_u32(smem);
    const int tid = threadIdx.x, wid = tid >> 5, lane = tid & 31;
    const int wm = wid / WARPS_N, wn = wid % WARPS_N;
    const int t = blockIdx.z, n0 = blockIdx.x * BN, m0 = blockIdx.y * BM;

    const int kq = tid % KQL, rowb = tid / KQL;
    const float* At = A + (size_t)t * a_t + (size_t)m0 * a_rs;
    const float* sArr = g_s + t * KTOT;
    const float* cArr = g_c + t * KTOT;
    const __half* WT = W + (size_t)t * KTOT * NTOT + n0;

    float4 areg[AV];
    float4 sv, cv;
    auto ldgA = [&](int kt) {
        const float* base = At + kt * BK + kq * 4;
        #pragma unroll
        for (int v = 0; v < AV; v++)
            areg[v] = *(const float4*)(base + (size_t)(rowb + v * RPV) * a_rs);
        sv = *(const float4*)(sArr + kt * BK + kq * 4);
        cv = *(const float4*)(cArr + kt * BK + kq * 4);
    };
    auto stsA = [&](int st) {
        char* hb = smem + st * STAGE;
        #pragma unroll
        for (int v = 0; v < AV; v++) {
            float y0 = fmaf(areg[v].x, sv.x, cv.x);
            float y1 = fmaf(areg[v].y, sv.y, cv.y);
            float y2 = fmaf(areg[v].z, sv.z, cv.z);
            float y3 = fmaf(areg[v].w, sv.w, cv.w);
            if (RELU) {
                y0 = fmaxf(y0, 0.f); y1 = fmaxf(y1, 0.f);
                y2 = fmaxf(y2, 0.f); y3 = fmaxf(y3, 0.f);
            }
            uint32_t off = (uint32_t)((rowb + v * RPV) * AROW + kq * 4) * 2;
            *(uint2*)(hb + off) = pack4h(y0, y1, y2, y3);
        }
    };
    auto cpW = [&](int kt, int st) {
        const uint32_t stb = sb + st * STAGE;
        #pragma unroll
        for (int i = tid; i < BK * SEGS; i += 256) {
            int row = i / SEGS, seg = i % SEGS;
            size_t g = (size_t)(kt * BK + row) * NTOT + seg * 8;
            cp16(stb + WHO + row * (WROW * 2) + seg * 16, WT + g);
        }
        asm volatile("cp.async.commit_group;" ::: "memory");
    };

    float acc[MT][NT][4];
    #pragma unroll
    for (int i = 0; i < MT; i++)
        #pragma unroll
        for (int j = 0; j < NT; j++)
            #pragma unroll
            for (int k = 0; k < 4; k++) acc[i][j][k] = 0.f;

    const int lrow = lane & 15, lsel = lane >> 4;

    auto compute_k16 = [&](uint32_t stb, int k16) {
        uint32_t ah[MT][4];
        #pragma unroll
        for (int mt = 0; mt < MT; mt++) {
            uint32_t off = (uint32_t)((wm * WTM + mt * 16 + lrow) * AROW +
                                      k16 * 16 + lsel * 8) * 2;
            ldm_x4(ah[mt], stb + off);
        }
        uint32_t bq[NT][2];
        #pragma unroll
        for (int np = 0; np < NT / 2; np++) {
            uint32_t off = (uint32_t)((k16 * 16 + lrow) * WROW + wn * WTN +
                                      np * 16 + lsel * 8) * 2;
            uint32_t r[4];
            ldm_x4t(r, stb + WHO + off);
            bq[2*np][0] = r[0]; bq[2*np][1] = r[1];
            bq[2*np+1][0] = r[2]; bq[2*np+1][1] = r[3];
        }
        #pragma unroll
        for (int mt = 0; mt < MT; mt++)
            #pragma unroll
            for (int nt = 0; nt < NT; nt++) mma_f16(acc[mt][nt], ah[mt], bq[nt]);
    };

    // prologue
    ldgA(0);
    cpW(0, 0);
    stsA(0);

    #pragma unroll 1
    for (int kt = 0; kt < KT; kt++) {
        const int st = kt & 1;
        asm volatile("cp.async.wait_group 0;" ::: "memory");
        __syncthreads();
        const bool more = (kt + 1 < KT);
        if (more) { cpW(kt + 1, st ^ 1); ldgA(kt + 1); }
        const uint32_t stb = sb + st * STAGE;
        compute_k16(stb, 0);
        if (more) stsA(st ^ 1);      // overlapped: writes the other stage
        #pragma unroll
        for (int k16 = 1; k16 < NK16; k16++) compute_k16(stb, k16);
    }
    __syncthreads();   // smem reused below for stats

    // ---- epilogue: bias, store, optional column stats ----
    const int r0 = lane >> 2, c0 = (lane & 3) * 2;
    #pragma unroll
    for (int nt = 0; nt < NT; nt++) {
        float2 bv = *(const float2*)(bias + t * NTOT + n0 + wn * WTN + nt * 8 + c0);
        #pragma unroll
        for (int mt = 0; mt < MT; mt++) {
            acc[mt][nt][0] += bv.x; acc[mt][nt][1] += bv.y;
            acc[mt][nt][2] += bv.x; acc[mt][nt][3] += bv.y;
        }
    }
    #pragma unroll
    for (int mt = 0; mt < MT; mt++) {
        #pragma unroll
        for (int nt = 0; nt < NT; nt++) {
            int col = n0 + wn * WTN + nt * 8 + c0;
            int row = m0 + wm * WTM + mt * 16 + r0;
            float* p0 = out + (size_t)t * o_t + (size_t)row * o_rs + col;
            float* p1 = p0 + (size_t)8 * o_rs;
            *(float2*)p0 = make_float2(acc[mt][nt][0], acc[mt][nt][1]);
            *(float2*)p1 = make_float2(acc[mt][nt][2], acc[mt][nt][3]);
        }
    }
    if (STATS) {
        float* sbuf = (float*)smem;   // [2 wm][2 kind][BN]
        #pragma unroll
        for (int nt = 0; nt < NT; nt++) {
            #pragma unroll
            for (int j = 0; j < 2; j++) {
                float s = 0.f, q = 0.f;
                #pragma unroll
                for (int mt = 0; mt < MT; mt++) {
                    float v0 = acc[mt][nt][j], v1 = acc[mt][nt][2 + j];
                    s += v0 + v1;
                    q = fmaf(v0, v0, q); q = fmaf(v1, v1, q);
                }
                #pragma unroll
                for (int msk = 4; msk <= 16; msk <<= 1) {
                    s += __shfl_xor_sync(0xffffffffu, s, msk);
                    q += __shfl_xor_sync(0xffffffffu, q, msk);
                }
                if (r0 == 0) {
                    int col = wn * WTN + nt * 8 + c0 + j;
                    sbuf[(wm * 2 + 0) * BN + col] = s;
                    sbuf[(wm * 2 + 1) * BN + col] = q;
                }
            }
        }
        __syncthreads();
        for (int cix = tid; cix < BN; cix += 256) {
            float ss = sbuf[0 * BN + cix] + sbuf[2 * BN + cix];
            float qq = sbuf[1 * BN + cix] + sbuf[3 * BN + cix];
            size_t pi = (size_t)blockIdx.y * (TT * NTOT) + (size_t)t * NTOT + n0 + cix;
            g_psum[pi] = ss;
            g_psq [pi] = qq;
        }
    }
}

// ---------------- launch --------------------------------------------------------
extern "C" void kernel_launch(void* const* d_in, const int* in_sizes, int n_in,
                              void* d_out, int out_size) {
    (void)in_sizes; (void)n_in; (void)out_size;
    const float* prices = (const float*)d_in[0];
    const float* bn0_g  = (const float*)d_in[1];
    const float* bn0_b  = (const float*)d_in[2];
    const float* W1     = (const float*)d_in[3];
    const float* b1     = (const float*)d_in[4];
    const float* bn1_g  = (const float*)d_in[5];
    const float* bn1_b  = (const float*)d_in[6];
    const float* W2     = (const float*)d_in[7];
    const float* b2     = (const float*)d_in[8];
    const float* bn2_g  = (const float*)d_in[9];
    const float* bn2_b  = (const float*)d_in[10];
    const float* W3     = (const float*)d_in[11];
    const float* b3     = (const float*)d_in[12];
    float* out = (float*)d_out;

    float* hp;
    __half *w1, *w2, *w3;
    cudaGetSymbolAddress((void**)&hp, g_h);
    cudaGetSymbolAddress((void**)&w1, g_w1);
    cudaGetSymbolAddress((void**)&w2, g_w2);
    cudaGetSymbolAddress((void**)&w3, g_w3);

    const float invB = 1.0f / (float)BB;

    auto g1 = gemm_mma<256, 64, 64,  512, false, true>;
    auto g2 = gemm_mma<256, 64, 512, 512, true,  true>;
    auto g3 = gemm_mma<64,  64, 512, 64,  true,  false>;
    // STAGE: 128*72*2 + 64*(BN+8)*2
    constexpr int STAGE_256 = 128 * 72 * 2 + 64 * 264 * 2;  // 52224
    constexpr int STAGE_64  = 128 * 72 * 2 + 64 * 72 * 2;   // 27648
    constexpr int SM1 = 1 * STAGE_256;    // KT=1 -> single stage
    constexpr int SM2 = 2 * STAGE_256;    // 104448
    constexpr int SM3 = 2 * STAGE_64;     // 55296
    cudaFuncSetAttribute(g1, cudaFuncAttributeMaxDynamicSharedMemorySize, SM1);
    cudaFuncSetAttribute(g2, cudaFuncAttributeMaxDynamicSharedMemorySize, SM2);
    cudaFuncSetAttribute(g3, cudaFuncAttributeMaxDynamicSharedMemorySize, SM3);

    // --- stage 0 + gemm1 (ordered so g1 is the 4th launch -> ncu captures it) ---
    prep_w<<<(int)(((size_t)TT*PP*HH/4 + 255)/256), 256>>>(W1, w1, (size_t)TT*PP*HH/4);
    stats_kernel<<<dim3(TT, SPLITS0), 64>>>(prices, (size_t)PP, TT * PP, PP,
                                            BB / SPLITS0);
    finalize_kernel<<<(TT * PP + 255) / 256, 256>>>(bn0_g, bn0_b, TT * PP, invB,
                                                    SPLITS0);
    g1<<<dim3(HH / 256, BB / 128, TT), 256, SM1>>>(
        prices, (size_t)PP, TT * PP, w1, b1, hp, (size_t)BB * HH, HH);

    // --- stage 1 + gemm2 ---
    prep_w<<<(int)(((size_t)TT*HH*HH/4 + 255)/256), 256>>>(W2, w2, (size_t)TT*HH*HH/4);
    finalize_kernel<<<(TT * HH + 255) / 256, 256>>>(bn1_g, bn1_b, TT * HH, invB,
                                                    MBLK);
    g2<<<dim3(HH / 256, BB / 128, TT), 256, SM2>>>(
        hp, (size_t)BB * HH, HH, w2, b2, hp, (size_t)BB * HH, HH);

    // --- stage 2 + gemm3 ---
    prep_w<<<(int)(((size_t)TT*HH*PP/4 + 255)/256), 256>>>(W3, w3, (size_t)TT*HH*PP/4);
    finalize_kernel<<<(TT * HH + 255) / 256, 256>>>(bn2_g, bn2_b, TT * HH, invB,
                                                    MBLK);
    g3<<<dim3(1, BB / 128, TT), 256, SM3>>>(
        hp, (size_t)BB * HH, HH, w3, b3, out, (size_t)PP, TT * PP);
}

// round 10
// speedup vs baseline: 4.3940x; 1.0420x over previous
#include <cuda_runtime.h>
#include <cuda_fp16.h>
#include <cstdint>

// ============================================================================
// RNN_BN_simple, round 10: single-product fp16 HMMA + fp16 h1 storage.
//  - h1 (biggest traffic stream: 537MB write + 1074MB read) stored as fp16,
//    halving ~1.6GB of HBM traffic. BN1 stats still fp32 (epilogue accs).
//  - GEMM templated on A-type (fp32 or fp16 gmem) and out-type.
//  - BN=256/BK=64 tile, BN affine (+ReLU) + fp16 convert in the GEMM
//    A-prologue overlapped under the first k16; BN stats in epilogue.
// ============================================================================

namespace {
constexpr int BB = 4096, TT = 64, PP = 64, HH = 512;
constexpr float BN_EPS = 1e-3f;
constexpr int SPLITS0 = 32;
constexpr int MBLK = BB / 128;
}

// ---------------- scratch ----------------------------------------------------
__device__ __align__(16) __half g_h1[(size_t)TT * BB * HH];   // fp16 h1
__device__ float g_h2[(size_t)TT * BB * HH];                   // fp32 h2
__device__ float g_psum[MBLK * TT * HH];
__device__ float g_psq [MBLK * TT * HH];
__device__ float g_s[TT * HH];
__device__ float g_c[TT * HH];
__device__ __align__(16) __half g_w1[(size_t)TT * PP * HH];
__device__ __align__(16) __half g_w2[(size_t)TT * HH * HH];
__device__ __align__(16) __half g_w3[(size_t)TT * HH * PP];

// ---------------- helpers ------------------------------------------------------
__device__ __forceinline__ uint32_t smem_u32(const void* p) {
    uint32_t a;
    asm("{ .reg .u64 t; cvta.to.shared.u64 t, %1; cvt.u32.u64 %0, t; }"
        : "=r"(a) : "l"(p));
    return a;
}
__device__ __forceinline__ void ldm_x4(uint32_t* r, uint32_t addr) {
    asm volatile("ldmatrix.sync.aligned.m8n8.x4.shared.b16 {%0,%1,%2,%3}, [%4];"
                 : "=r"(r[0]), "=r"(r[1]), "=r"(r[2]), "=r"(r[3]) : "r"(addr));
}
__device__ __forceinline__ void ldm_x4t(uint32_t* r, uint32_t addr) {
    asm volatile("ldmatrix.sync.aligned.m8n8.x4.trans.shared.b16 {%0,%1,%2,%3}, [%4];"
                 : "=r"(r[0]), "=r"(r[1]), "=r"(r[2]), "=r"(r[3]) : "r"(addr));
}
__device__ __forceinline__ void mma_f16(float* c, const uint32_t* a,
                                        const uint32_t* b) {
    asm volatile(
        "mma.sync.aligned.m16n8k16.row.col.f32.f16.f16.f32 "
        "{%0,%1,%2,%3}, {%4,%5,%6,%7}, {%8,%9}, {%0,%1,%2,%3};"
        : "+f"(c[0]), "+f"(c[1]), "+f"(c[2]), "+f"(c[3])
        : "r"(a[0]), "r"(a[1]), "r"(a[2]), "r"(a[3]), "r"(b[0]), "r"(b[1]));
}
__device__ __forceinline__ void cp16(uint32_t dst, const void* src) {
    asm volatile("cp.async.cg.shared.global [%0], [%1], 16;"
                 :: "r"(dst), "l"(src));
}
__device__ __forceinline__ uint2 pack4h(float y0, float y1, float y2, float y3) {
    __half2 h01 = __floats2half2_rn(y0, y1);
    __half2 h23 = __floats2half2_rn(y2, y3);
    return make_uint2(*reinterpret_cast<uint32_t*>(&h01),
                      *reinterpret_cast<uint32_t*>(&h23));
}

// A-vector type per gmem dtype: 4 elements per vector
template <typename T> struct avec;
template <> struct avec<float>  { using type = float4; };
template <> struct avec<__half> { using type = uint2;  };

__device__ __forceinline__ void unpack4(const float4& v, float& a, float& b,
                                        float& c, float& d) {
    a = v.x; b = v.y; c = v.z; d = v.w;
}
__device__ __forceinline__ void unpack4(const uint2& v, float& a, float& b,
                                        float& c, float& d) {
    __half2 p01 = *reinterpret_cast<const __half2*>(&v.x);
    __half2 p23 = *reinterpret_cast<const __half2*>(&v.y);
    float2 f01 = __half22float2(p01);
    float2 f23 = __half22float2(p23);
    a = f01.x; b = f01.y; c = f23.x; d = f23.y;
}
__device__ __forceinline__ void store2(float* p, float a, float b) {
    *(float2*)p = make_float2(a, b);
}
__device__ __forceinline__ void store2(__half* p, float a, float b) {
    *(__half2*)p = __floats2half2_rn(a, b);
}

// ---------------- BN stats for prices ------------------------------------------
__global__ void stats_kernel(const float* __restrict__ x, size_t t_stride,
                             int row_stride, int D, int rows_per_split) {
    const int t = blockIdx.x, split = blockIdx.y;
    const float* xt = x + (size_t)t * t_stride +
                      (size_t)split * rows_per_split * row_stride;
    for (int d = threadIdx.x; d < D; d += blockDim.x) {
        float s0 = 0.f, s1 = 0.f, q0 = 0.f, q1 = 0.f;
        #pragma unroll 2
        for (int r = 0; r < rows_per_split; r += 2) {
            float v0 = xt[(size_t)r * row_stride + d];
            float v1 = xt[(size_t)(r + 1) * row_stride + d];
            s0 += v0; q0 = fmaf(v0, v0, q0);
            s1 += v1; q1 = fmaf(v1, v1, q1);
        }
        int n = gridDim.x * D, i = t * D + d;
        g_psum[split * n + i] = s0 + s1;
        g_psq [split * n + i] = q0 + q1;
    }
}
__global__ void finalize_kernel(const float* __restrict__ gamma,
                                const float* __restrict__ beta, int n,
                                float invB, int nparts) {
    int i = blockIdx.x * blockDim.x + threadIdx.x;
    if (i >= n) return;
    float s = 0.f, q = 0.f;
    for (int sp = 0; sp < nparts; sp++) {
        s += g_psum[(size_t)sp * n + i];
        q += g_psq [(size_t)sp * n + i];
    }
    float m = s * invB;
    float v = fmaxf(fmaf(-m, m, q * invB), 0.f);
    float sc = gamma[i] * rsqrtf(v + BN_EPS);
    g_s[i] = sc;
    g_c[i] = fmaf(-m, sc, beta[i]);
}

// ---------------- weight prep: fp32 -> single rn fp16 ----------------------------
__global__ void prep_w(const float* __restrict__ W, __half* __restrict__ wh,
                       size_t nq) {
    size_t i = (size_t)blockIdx.x * blockDim.x + threadIdx.x;
    if (i >= nq) return;
    float4 w = ((const float4*)W)[i];
    ((uint2*)wh)[i] = pack4h(w.x, w.y, w.z, w.w);
}

// ---------------- single-product fp16 HMMA GEMM -----------------------------------
// out[t,m,n] = sum_k prelu(A[t,m,k]*s+c) * W[t,k,n] + bias[t,n]
template <int BN, int BK, int KTOT, int NTOT, bool RELU, bool STATS,
          typename AT, typename OT>
__global__ void __launch_bounds__(256)
gemm_mma(const AT* __restrict__ A, size_t a_t, int a_rs,
         const __half* __restrict__ W,
         const float* __restrict__ bias,
         OT* __restrict__ out, size_t o_t, int o_rs) {
    using AVec = typename avec<AT>::type;
    constexpr int BM = 128;
    constexpr int AROW = BK + 8, WROW = BN + 8;
    constexpr int A_BYTES = BM * AROW * 2, W_BYTES = BK * WROW * 2;
    constexpr int WHO = A_BYTES;
    constexpr int STAGE = A_BYTES + W_BYTES;
    constexpr int KT = KTOT / BK;
    constexpr int WARPS_M = 2, WARPS_N = 4;
    constexpr int WTM = BM / WARPS_M, WTN = BN / WARPS_N;
    constexpr int MT = WTM / 16, NT = WTN / 8;
    constexpr int SEGS = BN / 8;
    constexpr int AV = BM * BK / (4 * 256);
    constexpr int KQL = BK / 4;
    constexpr int RPV = 256 / KQL;
    constexpr int NK16 = BK / 16;

    extern __shared__ char smem[];
    const uint32_t sb = smem_u32(smem);
    const int tid = threadIdx.x, wid = tid >> 5, lane = tid & 31;
    const int wm = wid / WARPS_N, wn = wid % WARPS_N;
    const int t = blockIdx.z, n0 = blockIdx.x * BN, m0 = blockIdx.y * BM;

    const int kq = tid % KQL, rowb = tid / KQL;
    const AT* At = A + (size_t)t * a_t + (size_t)m0 * a_rs;
    const float* sArr = g_s + t * KTOT;
    const float* cArr = g_c + t * KTOT;
    const __half* WT = W + (size_t)t * KTOT * NTOT + n0;

    AVec areg[AV];
    float4 sv, cv;
    auto ldgA = [&](int kt) {
        const AT* base = At + kt * BK + kq * 4;
        #pragma unroll
        for (int v = 0; v < AV; v++)
            areg[v] = *(const AVec*)(base + (size_t)(rowb + v * RPV) * a_rs);
        sv = *(const float4*)(sArr + kt * BK + kq * 4);
        cv = *(const float4*)(cArr + kt * BK + kq * 4);
    };
    auto stsA = [&](int st) {
        char* hb = smem + st * STAGE;
        #pragma unroll
        for (int v = 0; v < AV; v++) {
            float x0, x1, x2, x3;
            unpack4(areg[v], x0, x1, x2, x3);
            float y0 = fmaf(x0, sv.x, cv.x);
            float y1 = fmaf(x1, sv.y, cv.y);
            float y2 = fmaf(x2, sv.z, cv.z);
            float y3 = fmaf(x3, sv.w, cv.w);
            if (RELU) {
                y0 = fmaxf(y0, 0.f); y1 = fmaxf(y1, 0.f);
                y2 = fmaxf(y2, 0.f); y3 = fmaxf(y3, 0.f);
            }
            uint32_t off = (uint32_t)((rowb + v * RPV) * AROW + kq * 4) * 2;
            *(uint2*)(hb + off) = pack4h(y0, y1, y2, y3);
        }
    };
    auto cpW = [&](int kt, int st) {
        const uint32_t stb = sb + st * STAGE;
        #pragma unroll
        for (int i = tid; i < BK * SEGS; i += 256) {
            int row = i / SEGS, seg = i % SEGS;
            size_t g = (size_t)(kt * BK + row) * NTOT + seg * 8;
            cp16(stb + WHO + row * (WROW * 2) + seg * 16, WT + g);
        }
        asm volatile("cp.async.commit_group;" ::: "memory");
    };

    float acc[MT][NT][4];
    #pragma unroll
    for (int i = 0; i < MT; i++)
        #pragma unroll
        for (int j = 0; j < NT; j++)
            #pragma unroll
            for (int k = 0; k < 4; k++) acc[i][j][k] = 0.f;

    const int lrow = lane & 15, lsel = lane >> 4;

    auto compute_k16 = [&](uint32_t stb, int k16) {
        uint32_t ah[MT][4];
        #pragma unroll
        for (int mt = 0; mt < MT; mt++) {
            uint32_t off = (uint32_t)((wm * WTM + mt * 16 + lrow) * AROW +
                                      k16 * 16 + lsel * 8) * 2;
            ldm_x4(ah[mt], stb + off);
        }
        uint32_t bq[NT][2];
        #pragma unroll
        for (int np = 0; np < NT / 2; np++) {
            uint32_t off = (uint32_t)((k16 * 16 + lrow) * WROW + wn * WTN +
                                      np * 16 + lsel * 8) * 2;
            uint32_t r[4];
            ldm_x4t(r, stb + WHO + off);
            bq[2*np][0] = r[0]; bq[2*np][1] = r[1];
            bq[2*np+1][0] = r[2]; bq[2*np+1][1] = r[3];
        }
        #pragma unroll
        for (int mt = 0; mt < MT; mt++)
            #pragma unroll
            for (int nt = 0; nt < NT; nt++) mma_f16(acc[mt][nt], ah[mt], bq[nt]);
    };

    // prologue
    ldgA(0);
    cpW(0, 0);
    stsA(0);

    #pragma unroll 1
    for (int kt = 0; kt < KT; kt++) {
        const int st = kt & 1;
        asm volatile("cp.async.wait_group 0;" ::: "memory");
        __syncthreads();
        const bool more = (kt + 1 < KT);
        if (more) { cpW(kt + 1, st ^ 1); ldgA(kt + 1); }
        const uint32_t stb = sb + st * STAGE;
        compute_k16(stb, 0);
        if (more) stsA(st ^ 1);      // overlapped: writes the other stage
        #pragma unroll
        for (int k16 = 1; k16 < NK16; k16++) compute_k16(stb, k16);
    }
    __syncthreads();   // smem reused below for stats

    // ---- epilogue: bias, store, optional column stats ----
    const int r0 = lane >> 2, c0 = (lane & 3) * 2;
    #pragma unroll
    for (int nt = 0; nt < NT; nt++) {
        float2 bv = *(const float2*)(bias + t * NTOT + n0 + wn * WTN + nt * 8 + c0);
        #pragma unroll
        for (int mt = 0; mt < MT; mt++) {
            acc[mt][nt][0] += bv.x; acc[mt][nt][1] += bv.y;
            acc[mt][nt][2] += bv.x; acc[mt][nt][3] += bv.y;
        }
    }
    #pragma unroll
    for (int mt = 0; mt < MT; mt++) {
        #pragma unroll
        for (int nt = 0; nt < NT; nt++) {
            int col = n0 + wn * WTN + nt * 8 + c0;
            int row = m0 + wm * WTM + mt * 16 + r0;
            OT* p0 = out + (size_t)t * o_t + (size_t)row * o_rs + col;
            OT* p1 = p0 + (size_t)8 * o_rs;
            store2(p0, acc[mt][nt][0], acc[mt][nt][1]);
            store2(p1, acc[mt][nt][2], acc[mt][nt][3]);
        }
    }
    if (STATS) {
        float* sbuf = (float*)smem;   // [2 wm][2 kind][BN]
        #pragma unroll
        for (int nt = 0; nt < NT; nt++) {
            #pragma unroll
            for (int j = 0; j < 2; j++) {
                float s = 0.f, q = 0.f;
                #pragma unroll
                for (int mt = 0; mt < MT; mt++) {
                    float v0 = acc[mt][nt][j], v1 = acc[mt][nt][2 + j];
                    s += v0 + v1;
                    q = fmaf(v0, v0, q); q = fmaf(v1, v1, q);
                }
                #pragma unroll
                for (int msk = 4; msk <= 16; msk <<= 1) {
                    s += __shfl_xor_sync(0xffffffffu, s, msk);
                    q += __shfl_xor_sync(0xffffffffu, q, msk);
                }
                if (r0 == 0) {
                    int col = wn * WTN + nt * 8 + c0 + j;
                    sbuf[(wm * 2 + 0) * BN + col] = s;
                    sbuf[(wm * 2 + 1) * BN + col] = q;
                }
            }
        }
        __syncthreads();
        for (int cix = tid; cix < BN; cix += 256) {
            float ss = sbuf[0 * BN + cix] + sbuf[2 * BN + cix];
            float qq = sbuf[1 * BN + cix] + sbuf[3 * BN + cix];
            size_t pi = (size_t)blockIdx.y * (TT * NTOT) + (size_t)t * NTOT + n0 + cix;
            g_psum[pi] = ss;
            g_psq [pi] = qq;
        }
    }
}

// ---------------- launch --------------------------------------------------------
extern "C" void kernel_launch(void* const* d_in, const int* in_sizes, int n_in,
                              void* d_out, int out_size) {
    (void)in_sizes; (void)n_in; (void)out_size;
    const float* prices = (const float*)d_in[0];
    const float* bn0_g  = (const float*)d_in[1];
    const float* bn0_b  = (const float*)d_in[2];
    const float* W1     = (const float*)d_in[3];
    const float* b1     = (const float*)d_in[4];
    const float* bn1_g  = (const float*)d_in[5];
    const float* bn1_b  = (const float*)d_in[6];
    const float* W2     = (const float*)d_in[7];
    const float* b2     = (const float*)d_in[8];
    const float* bn2_g  = (const float*)d_in[9];
    const float* bn2_b  = (const float*)d_in[10];
    const float* W3     = (const float*)d_in[11];
    const float* b3     = (const float*)d_in[12];
    float* out = (float*)d_out;

    __half* hp1;
    float* hp2;
    __half *w1, *w2, *w3;
    cudaGetSymbolAddress((void**)&hp1, g_h1);
    cudaGetSymbolAddress((void**)&hp2, g_h2);
    cudaGetSymbolAddress((void**)&w1, g_w1);
    cudaGetSymbolAddress((void**)&w2, g_w2);
    cudaGetSymbolAddress((void**)&w3, g_w3);

    const float invB = 1.0f / (float)BB;

    auto g1 = gemm_mma<256, 64, 64,  512, false, true,  float,  __half>;
    auto g2 = gemm_mma<256, 64, 512, 512, true,  true,  __half, float>;
    auto g3 = gemm_mma<64,  64, 512, 64,  true,  false, float,  float>;
    // STAGE: 128*72*2 + 64*(BN+8)*2
    constexpr int STAGE_256 = 128 * 72 * 2 + 64 * 264 * 2;  // 52224
    constexpr int STAGE_64  = 128 * 72 * 2 + 64 * 72 * 2;   // 27648
    constexpr int SM1 = 1 * STAGE_256;    // KT=1 -> single stage
    constexpr int SM2 = 2 * STAGE_256;    // 104448
    constexpr int SM3 = 2 * STAGE_64;     // 55296
    cudaFuncSetAttribute(g1, cudaFuncAttributeMaxDynamicSharedMemorySize, SM1);
    cudaFuncSetAttribute(g2, cudaFuncAttributeMaxDynamicSharedMemorySize, SM2);
    cudaFuncSetAttribute(g3, cudaFuncAttributeMaxDynamicSharedMemorySize, SM3);

    // --- stage 0 + gemm1 (g1 is the 4th launch -> ncu captures it) ---
    prep_w<<<(int)(((size_t)TT*PP*HH/4 + 255)/256), 256>>>(W1, w1, (size_t)TT*PP*HH/4);
    stats_kernel<<<dim3(TT, SPLITS0), 64>>>(prices, (size_t)PP, TT * PP, PP,
                                            BB / SPLITS0);
    finalize_kernel<<<(TT * PP + 255) / 256, 256>>>(bn0_g, bn0_b, TT * PP, invB,
                                                    SPLITS0);
    g1<<<dim3(HH / 256, BB / 128, TT), 256, SM1>>>(
        prices, (size_t)PP, TT * PP, w1, b1, hp1, (size_t)BB * HH, HH);

    // --- stage 1 + gemm2 ---
    prep_w<<<(int)(((size_t)TT*HH*HH/4 + 255)/256), 256>>>(W2, w2, (size_t)TT*HH*HH/4);
    finalize_kernel<<<(TT * HH + 255) / 256, 256>>>(bn1_g, bn1_b, TT * HH, invB,
                                                    MBLK);
    g2<<<dim3(HH / 256, BB / 128, TT), 256, SM2>>>(
        hp1, (size_t)BB * HH, HH, w2, b2, hp2, (size_t)BB * HH, HH);

    // --- stage 2 + gemm3 ---
    prep_w<<<(int)(((size_t)TT*HH*PP/4 + 255)/256), 256>>>(W3, w3, (size_t)TT*HH*PP/4);
    finalize_kernel<<<(TT * HH + 255) / 256, 256>>>(bn2_g, bn2_b, TT * HH, invB,
                                                    MBLK);
    g3<<<dim3(1, BB / 128, TT), 256, SM3>>>(
        hp2, (size_t)BB * HH, HH, w3, b3, out, (size_t)PP, TT * PP);
}